// round 7
// baseline (speedup 1.0000x reference)
#include <cuda_runtime.h>
#include <cuda_bf16.h>
#include <cstdint>

typedef unsigned long long u64;
typedef unsigned int       u32;

#define B_   8
#define V_   200
#define T_   128
#define NBLK (B_ * V_)          // 1600

// ---- smem byte offsets ----
#define OF_AFH  0               // A frags hi: u32[8tt][8kg][4reg][32lane] = 32KB (input; later AO)
#define OF_AFL  32768
#define OF_BFH  65536           // B frags hi: u32[8ot][8kg][2reg][32lane] = 16KB
#define OF_BFL  81920
#define OF_AQH  98304           // Q A-frags k8: u32[8h][8tt][2reg][32] = 16KB
#define OF_AQL  114688
#define OF_BKH  131072          // K B-frags k8: u32[8h][16si][32] = 16KB
#define OF_BKL  147456
#define OF_VBH  163840          // V B-frags k16: u32[8h][8kg][2reg][32] = 16KB
#define OF_VBL  180224
#define OF_BIAS 196608          // 256 floats
#define SMEM_TOTAL 197632

// ---- helpers ----
__device__ __forceinline__ u32 pack_bf(float a, float b) {
    __nv_bfloat162 h = __floats2bfloat162_rn(a, b);   // .x = a (low), .y = b (high)
    u32 r; asm("mov.b32 %0, %1;" : "=r"(r) : "r"(*(u32*)&h)); return r;
}
__device__ __forceinline__ float bfr(float a) {
    return __bfloat162float(__float2bfloat16(a));
}
// pack (a,b) to bf16x2 hi + residual bf16x2 lo
__device__ __forceinline__ void split2(float a, float b, u32& hi, u32& lo) {
    hi = pack_bf(a, b);
    float ra = __uint_as_float(hi << 16);
    float rb = __uint_as_float(hi & 0xFFFF0000u);
    lo = pack_bf(a - ra, b - rb);
}
// m16n8k16 row.col bf16 -> f32, D += A*B
__device__ __forceinline__ void mma16816(float* c, const u32* a, const u32* b) {
    asm volatile(
        "mma.sync.aligned.m16n8k16.row.col.f32.bf16.bf16.f32 "
        "{%0,%1,%2,%3}, {%4,%5,%6,%7}, {%8,%9}, {%0,%1,%2,%3};"
        : "+f"(c[0]), "+f"(c[1]), "+f"(c[2]), "+f"(c[3])
        : "r"(a[0]), "r"(a[1]), "r"(a[2]), "r"(a[3]), "r"(b[0]), "r"(b[1]));
}
// m16n8k8 row.col bf16 -> f32, D += A*B
__device__ __forceinline__ void mma16808(float* c, const u32* a, u32 b) {
    asm volatile(
        "mma.sync.aligned.m16n8k8.row.col.f32.bf16.bf16.f32 "
        "{%0,%1,%2,%3}, {%4,%5}, {%6}, {%0,%1,%2,%3};"
        : "+f"(c[0]), "+f"(c[1]), "+f"(c[2]), "+f"(c[3])
        : "r"(a[0]), "r"(a[1]), "r"(b));
}
__device__ __forceinline__ void vstore(char* bh, char* bl, int off, float v) {
    __nv_bfloat16 h = __float2bfloat16(v);
    *(__nv_bfloat16*)(bh + off) = h;
    *(__nv_bfloat16*)(bl + off) = __float2bfloat16(v - __bfloat162float(h));
}

extern __shared__ char smc[];

__global__ __launch_bounds__(512, 1) void tatt_hmma(
    const float* __restrict__ x,  const float* __restrict__ tem,
    const float* __restrict__ Wq, const float* __restrict__ bq,
    const float* __restrict__ Wk, const float* __restrict__ bk,
    const float* __restrict__ Wv, const float* __restrict__ bv,
    const float* __restrict__ Wo, const float* __restrict__ bo,
    float* __restrict__ out)
{
    u32*   AFH  = (u32*)(smc + OF_AFH);
    u32*   AFL  = (u32*)(smc + OF_AFL);
    u32*   BFH  = (u32*)(smc + OF_BFH);
    u32*   BFL  = (u32*)(smc + OF_BFL);
    u32*   AQH  = (u32*)(smc + OF_AQH);
    u32*   AQL  = (u32*)(smc + OF_AQL);
    u32*   BKH  = (u32*)(smc + OF_BKH);
    u32*   BKL  = (u32*)(smc + OF_BKL);
    u32*   VBH  = (u32*)(smc + OF_VBH);
    u32*   VBL  = (u32*)(smc + OF_VBL);
    float* bias = (float*)(smc + OF_BIAS);

    const int tid = threadIdx.x, lane = tid & 31, w = tid >> 5;
    const int blk = blockIdx.x, b = blk / V_, v = blk % V_;

    if (tid < 64) {
        bias[tid]       = bq[tid];
        bias[64 + tid]  = bk[tid];
        bias[128 + tid] = bv[tid];
        bias[192 + tid] = bo[tid];
    }

    // ---- stage concat input as A-fragments (hi/lo bf16 split) [validated R5] ----
    for (int i = tid; i < 8192; i += 512) {
        int cp = i >> 7, t = i & 127;
        int c0 = cp << 1;
        const float* src = (c0 < 64) ? x : tem;
        const float* pb = src + ((long)((b << 6) + (c0 & 63)) * V_ + v) * T_ + t;
        float g0 = pb[0];
        float g1 = pb[(long)V_ * T_];
        int tt = t >> 4, kg = cp >> 3, tin = t & 15;
        int lane_f = ((tin & 7) << 2) + (cp & 3);
        int reg = (tin >> 3) + (((cp >> 2) & 1) << 1);
        int X = (t >> 3) & 3;
        int idx = (((tt << 3) + kg) * 4 + reg) * 32 + (lane_f ^ X);
        AFH[idx] = pack_bf(g0, g1);
        AFL[idx] = pack_bf(g0 - bfr(g0), g1 - bfr(g1));
    }

    const int mt = w >> 2, nq = w & 3;
    const int gid = lane >> 2, tig = lane & 3;

    // ---- three projections (QKV) via HMMA, epilogue -> attention frags ----
    const float* Wsrc[3] = {Wq, Wk, Wv};
#pragma unroll 1
    for (int p = 0; p < 3; ++p) {
        for (int i = tid; i < 4096; i += 512) {
            int o = i >> 6, cp = i & 63;
            float2 g = *(const float2*)(Wsrc[p] + o * 128 + (cp << 1));
            int kg = cp >> 3;
            int lane_f = ((o & 7) << 2) + (cp & 3);
            int reg = (cp >> 2) & 1;
            int X = ((cp >> 2) & 7) << 2;
            int idx = ((((o >> 3) << 3) + kg) * 2 + reg) * 32 + (lane_f ^ X);
            BFH[idx] = pack_bf(g.x, g.y);
            BFL[idx] = pack_bf(g.x - bfr(g.x), g.y - bfr(g.y));
        }
        __syncthreads();

        float acc[2][2][4];
#pragma unroll
        for (int m2 = 0; m2 < 2; ++m2)
#pragma unroll
            for (int n2 = 0; n2 < 2; ++n2)
#pragma unroll
                for (int j = 0; j < 4; ++j) acc[m2][n2][j] = 0.f;

#pragma unroll
        for (int kg = 0; kg < 8; ++kg) {
            u32 Ah[2][4], Al[2][4], Bh[2][2], Bl[2][2];
#pragma unroll
            for (int m2 = 0; m2 < 2; ++m2) {
                int tt = mt * 2 + m2;
#pragma unroll
                for (int r = 0; r < 4; ++r) {
                    int X = (tt * 2 + (r & 1)) & 3;
                    int idx = ((tt * 8 + kg) * 4 + r) * 32 + (lane ^ X);
                    Ah[m2][r] = AFH[idx];
                    Al[m2][r] = AFL[idx];
                }
            }
#pragma unroll
            for (int n2 = 0; n2 < 2; ++n2) {
                int ot = nq * 2 + n2;
#pragma unroll
                for (int r = 0; r < 2; ++r) {
                    int X = ((kg * 2 + r) & 7) << 2;
                    int idx = ((ot * 8 + kg) * 2 + r) * 32 + (lane ^ X);
                    Bh[n2][r] = BFH[idx];
                    Bl[n2][r] = BFL[idx];
                }
            }
#pragma unroll
            for (int m2 = 0; m2 < 2; ++m2)
#pragma unroll
                for (int n2 = 0; n2 < 2; ++n2) {
                    mma16816(acc[m2][n2], Ah[m2], Bh[n2]);
                    mma16816(acc[m2][n2], Ah[m2], Bl[n2]);
                    mma16816(acc[m2][n2], Al[m2], Bh[n2]);
                }
        }

        // epilogue -> Q A-frags / K B-frags / V B-frags (hi/lo)
#pragma unroll
        for (int m2 = 0; m2 < 2; ++m2)
#pragma unroll
            for (int n2 = 0; n2 < 2; ++n2) {
                int TT = mt * 2 + m2, hh = nq * 2 + n2;
                int o0 = hh * 8 + (tig << 1);
                float b0 = bias[p * 64 + o0], b1 = bias[p * 64 + o0 + 1];
                float v0 = acc[m2][n2][0] + b0, v1 = acc[m2][n2][1] + b1;
                float v2 = acc[m2][n2][2] + b0, v3 = acc[m2][n2][3] + b1;
                if (p == 0) {
                    const float SC = 0.35355339059327373f;   // 1/sqrt(8)
                    v0 *= SC; v1 *= SC; v2 *= SC; v3 *= SC;
                    u32 hi, lo;
                    split2(v0, v1, hi, lo);
                    int i0 = ((hh * 8 + TT) * 2 + 0) * 32 + lane;
                    AQH[i0] = hi; AQL[i0] = lo;
                    split2(v2, v3, hi, lo);
                    int i1 = ((hh * 8 + TT) * 2 + 1) * 32 + lane;
                    AQH[i1] = hi; AQL[i1] = lo;
                } else if (p == 1) {
                    u32 hi, lo;
                    split2(v0, v1, hi, lo);
                    int i0 = (hh * 16 + TT * 2) * 32 + lane;
                    BKH[i0] = hi; BKL[i0] = lo;
                    split2(v2, v3, hi, lo);
                    int i1 = (hh * 16 + TT * 2 + 1) * 32 + lane;
                    BKH[i1] = hi; BKL[i1] = lo;
                } else {
                    // V transpose scatter: element (s=t, d) -> B-frag [h][kg=TT][reg][lane]
                    char* bh = smc + OF_VBH + hh * 2048 + TT * 256;
                    char* bl = smc + OF_VBL + hh * 2048 + TT * 256;
                    int d0 = tig << 1, d1 = d0 + 1;
                    int wo0 = d0 * 16 + ((gid >> 1) << 2) + ((gid & 1) << 1);
                    int wo1 = d1 * 16 + ((gid >> 1) << 2) + ((gid & 1) << 1);
                    vstore(bh, bl, wo0, v0);          // reg 0 (s_local = gid)
                    vstore(bh, bl, wo1, v1);
                    vstore(bh, bl, 128 + wo0, v2);    // reg 1 (s_local = gid+8)
                    vstore(bh, bl, 128 + wo1, v3);
                }
            }
        __syncthreads();
    }

    // ---- stage Wo[64][64] as B-fragments (kg 0..3) [validated R5] ----
    for (int i = tid; i < 2048; i += 512) {
        int o = i >> 5, cp = i & 31;
        float2 g = *(const float2*)(Wo + (o << 6) + (cp << 1));
        int kg = cp >> 3;
        int lane_f = ((o & 7) << 2) + (cp & 3);
        int reg = (cp >> 2) & 1;
        int X = ((cp >> 2) & 7) << 2;
        int idx = ((((o >> 3) << 2) + kg) * 2 + reg) * 32 + (lane_f ^ X);
        BFH[idx] = pack_bf(g.x, g.y);
        BFL[idx] = pack_bf(g.x - bfr(g.x), g.y - bfr(g.y));
    }

    // ---- tensor-core causal attention ----
    // warp: head h = w>>1, m-tiles mi = (w&1) + 2j (interleaved for balance)
    {
        const int h = w >> 1, half = w & 1;
        const bool m0 = (2 * tig) <= gid;
        const bool m1 = (2 * tig + 1) <= gid;

#pragma unroll 1
        for (int j = 0; j < 4; ++j) {
            const int mi = half + 2 * j;
            u32 qh[2], ql[2];
            qh[0] = AQH[((h * 8 + mi) * 2 + 0) * 32 + lane];
            qh[1] = AQH[((h * 8 + mi) * 2 + 1) * 32 + lane];
            ql[0] = AQL[((h * 8 + mi) * 2 + 0) * 32 + lane];
            ql[1] = AQL[((h * 8 + mi) * 2 + 1) * 32 + lane];

            float oa[4] = {0.f, 0.f, 0.f, 0.f};
            float l0 = 0.f, l1 = 0.f;

            for (int kg = 0; kg <= mi; ++kg) {
                float s0[4] = {0.f, 0.f, 0.f, 0.f};
                float s1[4] = {0.f, 0.f, 0.f, 0.f};
                u32 kh0 = BKH[(h * 16 + 2 * kg) * 32 + lane];
                u32 kl0 = BKL[(h * 16 + 2 * kg) * 32 + lane];
                u32 kh1 = BKH[(h * 16 + 2 * kg + 1) * 32 + lane];
                u32 kl1 = BKL[(h * 16 + 2 * kg + 1) * 32 + lane];
                mma16808(s0, qh, kh0); mma16808(s0, ql, kh0); mma16808(s0, qh, kl0);
                mma16808(s1, qh, kh1); mma16808(s1, ql, kh1); mma16808(s1, qh, kl1);

                float e00 = __expf(s0[0]), e01 = __expf(s0[1]);
                float e02 = __expf(s0[2]), e03 = __expf(s0[3]);
                float e10 = __expf(s1[0]), e11 = __expf(s1[1]);
                float e12 = __expf(s1[2]), e13 = __expf(s1[3]);
                if (kg == mi) {               // diagonal masking: s <= t
                    e00 = m0 ? e00 : 0.f; e01 = m1 ? e01 : 0.f;
                    e10 = 0.f;            e11 = 0.f;
                    e12 = m0 ? e12 : 0.f; e13 = m1 ? e13 : 0.f;
                }
                l0 += (e00 + e01) + (e10 + e11);
                l1 += (e02 + e03) + (e12 + e13);

                u32 ph[4], pl[4];
                split2(e00, e01, ph[0], pl[0]);
                split2(e02, e03, ph[1], pl[1]);
                split2(e10, e11, ph[2], pl[2]);
                split2(e12, e13, ph[3], pl[3]);

                u32 vh[2], vl[2];
                vh[0] = VBH[((h * 8 + kg) * 2 + 0) * 32 + lane];
                vh[1] = VBH[((h * 8 + kg) * 2 + 1) * 32 + lane];
                vl[0] = VBL[((h * 8 + kg) * 2 + 0) * 32 + lane];
                vl[1] = VBL[((h * 8 + kg) * 2 + 1) * 32 + lane];
                mma16816(oa, ph, vh);
                mma16816(oa, pl, vh);
                mma16816(oa, ph, vl);
            }

            l0 += __shfl_xor_sync(0xFFFFFFFFu, l0, 1);
            l0 += __shfl_xor_sync(0xFFFFFFFFu, l0, 2);
            l1 += __shfl_xor_sync(0xFFFFFFFFu, l1, 1);
            l1 += __shfl_xor_sync(0xFFFFFFFFu, l1, 2);
            float inv0 = __fdividef(1.f, l0), inv1 = __fdividef(1.f, l1);
            oa[0] *= inv0; oa[1] *= inv0; oa[2] *= inv1; oa[3] *= inv1;

            // store as out-proj A-frags (layout matches R5 out-proj loader)
            int kga = h >> 1, regb = (h & 1) << 1;
            int X0 = (mi * 2) & 3, X1 = (mi * 2 + 1) & 3;
            int base = (mi * 4 + kga) * 4;
            u32 hi, lo;
            split2(oa[0], oa[1], hi, lo);
            AFH[(base + regb) * 32 + (lane ^ X0)] = hi;
            AFL[(base + regb) * 32 + (lane ^ X0)] = lo;
            split2(oa[2], oa[3], hi, lo);
            AFH[(base + regb + 1) * 32 + (lane ^ X1)] = hi;
            AFL[(base + regb + 1) * 32 + (lane ^ X1)] = lo;
        }
    }
    __syncthreads();

    // ---- out projection (kg 0..3) + bias + ReLU -> global [validated R5] ----
    {
        float acc[2][2][4];
#pragma unroll
        for (int m2 = 0; m2 < 2; ++m2)
#pragma unroll
            for (int n2 = 0; n2 < 2; ++n2)
#pragma unroll
                for (int j = 0; j < 4; ++j) acc[m2][n2][j] = 0.f;

#pragma unroll
        for (int kg = 0; kg < 4; ++kg) {
            u32 Ah[2][4], Al[2][4], Bh[2][2], Bl[2][2];
#pragma unroll
            for (int m2 = 0; m2 < 2; ++m2) {
                int tt = mt * 2 + m2;
#pragma unroll
                for (int r = 0; r < 4; ++r) {
                    int X = (tt * 2 + (r & 1)) & 3;
                    int idx = ((tt * 4 + kg) * 4 + r) * 32 + (lane ^ X);
                    Ah[m2][r] = AFH[idx];
                    Al[m2][r] = AFL[idx];
                }
            }
#pragma unroll
            for (int n2 = 0; n2 < 2; ++n2) {
                int ot = nq * 2 + n2;
#pragma unroll
                for (int r = 0; r < 2; ++r) {
                    int X = ((kg * 2 + r) & 7) << 2;
                    int idx = ((ot * 4 + kg) * 2 + r) * 32 + (lane ^ X);
                    Bh[n2][r] = BFH[idx];
                    Bl[n2][r] = BFL[idx];
                }
            }
#pragma unroll
            for (int m2 = 0; m2 < 2; ++m2)
#pragma unroll
                for (int n2 = 0; n2 < 2; ++n2) {
                    mma16816(acc[m2][n2], Ah[m2], Bh[n2]);
                    mma16816(acc[m2][n2], Ah[m2], Bl[n2]);
                    mma16816(acc[m2][n2], Al[m2], Bh[n2]);
                }
        }

#pragma unroll
        for (int m2 = 0; m2 < 2; ++m2)
#pragma unroll
            for (int n2 = 0; n2 < 2; ++n2) {
                int t0 = ((mt * 2 + m2) << 4) + gid;
                int o0 = ((nq * 2 + n2) << 3) + (tig << 1);
                float b0 = bias[192 + o0], b1 = bias[192 + o0 + 1];
                long base0 = ((long)(b * 64 + o0) * V_ + v) * T_;
                long base1 = base0 + (long)V_ * T_;
                out[base0 + t0]     = fmaxf(acc[m2][n2][0] + b0, 0.f);
                out[base1 + t0]     = fmaxf(acc[m2][n2][1] + b1, 0.f);
                out[base0 + t0 + 8] = fmaxf(acc[m2][n2][2] + b0, 0.f);
                out[base1 + t0 + 8] = fmaxf(acc[m2][n2][3] + b1, 0.f);
            }
    }
}

// ---------------------------------------------------------------------------
extern "C" void kernel_launch(void* const* d_in, const int* in_sizes, int n_in,
                              void* d_out, int out_size)
{
    (void)in_sizes; (void)n_in; (void)out_size;
    const float* x  = (const float*)d_in[0];
    const float* te = (const float*)d_in[1];
    const float* Wq = (const float*)d_in[2];
    const float* bq = (const float*)d_in[3];
    const float* Wk = (const float*)d_in[4];
    const float* bk = (const float*)d_in[5];
    const float* Wv = (const float*)d_in[6];
    const float* bv = (const float*)d_in[7];
    const float* Wo = (const float*)d_in[8];
    const float* bo = (const float*)d_in[9];
    float* out = (float*)d_out;

    cudaFuncSetAttribute(tatt_hmma, cudaFuncAttributeMaxDynamicSharedMemorySize, SMEM_TOTAL);
    tatt_hmma<<<NBLK, 512, SMEM_TOTAL>>>(x, te, Wq, bq, Wk, bk, Wv, bv, Wo, bo, out);
}

// round 8
// speedup vs baseline: 1.4595x; 1.4595x over previous
#include <cuda_runtime.h>
#include <cuda_bf16.h>
#include <cstdint>

typedef unsigned long long u64;
typedef unsigned int       u32;

#define B_   8
#define V_   200
#define T_   128
#define NBLK (B_ * V_)          // 1600

// ---- smem byte offsets ----
#define OF_AFH  0               // A frags hi: u32[8tt][8kg][4reg][32lane] = 32KB (input; later AO)
#define OF_AFL  32768
#define OF_BFH  65536           // B frags hi: u32[8ot][8kg][2reg][32lane] = 16KB
#define OF_BFL  81920
#define OF_AQH  98304           // Q A-frags k8: u32[8h][8tt][2reg][32] = 16KB
#define OF_AQL  114688
#define OF_BKH  131072          // K B-frags k8: u32[8h][16si][32] = 16KB
#define OF_BKL  147456
#define OF_VBH  163840          // V B-frags k16: u32[8h][8kg][2reg][32] = 16KB
#define OF_VBL  180224
#define OF_BIAS 196608          // 256 floats
#define SMEM_TOTAL 197632

// ---- helpers ----
__device__ __forceinline__ u32 pack_bf(float a, float b) {
    __nv_bfloat162 h = __floats2bfloat162_rn(a, b);
    u32 r; asm("mov.b32 %0, %1;" : "=r"(r) : "r"(*(u32*)&h)); return r;
}
__device__ __forceinline__ float bfr(float a) {
    return __bfloat162float(__float2bfloat16(a));
}
__device__ __forceinline__ void split2(float a, float b, u32& hi, u32& lo) {
    hi = pack_bf(a, b);
    float ra = __uint_as_float(hi << 16);
    float rb = __uint_as_float(hi & 0xFFFF0000u);
    lo = pack_bf(a - ra, b - rb);
}
__device__ __forceinline__ void mma16816(float* c, const u32* a, const u32* b) {
    asm volatile(
        "mma.sync.aligned.m16n8k16.row.col.f32.bf16.bf16.f32 "
        "{%0,%1,%2,%3}, {%4,%5,%6,%7}, {%8,%9}, {%0,%1,%2,%3};"
        : "+f"(c[0]), "+f"(c[1]), "+f"(c[2]), "+f"(c[3])
        : "r"(a[0]), "r"(a[1]), "r"(a[2]), "r"(a[3]), "r"(b[0]), "r"(b[1]));
}
__device__ __forceinline__ void mma16808(float* c, const u32* a, u32 b) {
    asm volatile(
        "mma.sync.aligned.m16n8k8.row.col.f32.bf16.bf16.f32 "
        "{%0,%1,%2,%3}, {%4,%5}, {%6}, {%0,%1,%2,%3};"
        : "+f"(c[0]), "+f"(c[1]), "+f"(c[2]), "+f"(c[3])
        : "r"(a[0]), "r"(a[1]), "r"(b));
}
__device__ __forceinline__ void vstore(char* bh, char* bl, int off, float v) {
    __nv_bfloat16 h = __float2bfloat16(v);
    *(__nv_bfloat16*)(bh + off) = h;
    *(__nv_bfloat16*)(bl + off) = __float2bfloat16(v - __bfloat162float(h));
}

extern __shared__ char smc[];

__global__ __launch_bounds__(512, 1) void tatt_hmma(
    const float* __restrict__ x,  const float* __restrict__ tem,
    const float* __restrict__ Wq, const float* __restrict__ bq,
    const float* __restrict__ Wk, const float* __restrict__ bk,
    const float* __restrict__ Wv, const float* __restrict__ bv,
    const float* __restrict__ Wo, const float* __restrict__ bo,
    float* __restrict__ out)
{
    u32*   AFH  = (u32*)(smc + OF_AFH);
    u32*   AFL  = (u32*)(smc + OF_AFL);
    u32*   BFH  = (u32*)(smc + OF_BFH);
    u32*   BFL  = (u32*)(smc + OF_BFL);
    u32*   AQH  = (u32*)(smc + OF_AQH);
    u32*   AQL  = (u32*)(smc + OF_AQL);
    u32*   BKH  = (u32*)(smc + OF_BKH);
    u32*   BKL  = (u32*)(smc + OF_BKL);
    u32*   VBH  = (u32*)(smc + OF_VBH);
    u32*   VBL  = (u32*)(smc + OF_VBL);
    float* bias = (float*)(smc + OF_BIAS);

    const int tid = threadIdx.x, lane = tid & 31, w = tid >> 5;
    const int blk = blockIdx.x, b = blk / V_, v = blk % V_;

    if (tid < 64) {
        bias[tid]       = bq[tid];
        bias[64 + tid]  = bk[tid];
        bias[128 + tid] = bv[tid];
        bias[192 + tid] = bo[tid];
    }

    // ---- stage concat input as A-fragments (hi/lo bf16 split) [validated] ----
    for (int i = tid; i < 8192; i += 512) {
        int cp = i >> 7, t = i & 127;
        int c0 = cp << 1;
        const float* src = (c0 < 64) ? x : tem;
        const float* pb = src + ((long)((b << 6) + (c0 & 63)) * V_ + v) * T_ + t;
        float g0 = pb[0];
        float g1 = pb[(long)V_ * T_];
        int tt = t >> 4, kg = cp >> 3, tin = t & 15;
        int lane_f = ((tin & 7) << 2) + (cp & 3);
        int reg = (tin >> 3) + (((cp >> 2) & 1) << 1);
        int X = (t >> 3) & 3;
        int idx = (((tt << 3) + kg) * 4 + reg) * 32 + (lane_f ^ X);
        AFH[idx] = pack_bf(g0, g1);
        AFL[idx] = pack_bf(g0 - bfr(g0), g1 - bfr(g1));
    }

    const int mt = w >> 2, nq = w & 3;
    const int gid = lane >> 2, tig = lane & 3;

    // ---- three projections (QKV) via HMMA, epilogue -> attention frags ----
    const float* Wsrc[3] = {Wq, Wk, Wv};
#pragma unroll 1
    for (int p = 0; p < 3; ++p) {
        for (int i = tid; i < 4096; i += 512) {
            int o = i >> 6, cp = i & 63;
            float2 g = *(const float2*)(Wsrc[p] + o * 128 + (cp << 1));
            int kg = cp >> 3;
            int lane_f = ((o & 7) << 2) + (cp & 3);
            int reg = (cp >> 2) & 1;
            int X = ((cp >> 2) & 7) << 2;
            int idx = ((((o >> 3) << 3) + kg) * 2 + reg) * 32 + (lane_f ^ X);
            BFH[idx] = pack_bf(g.x, g.y);
            BFL[idx] = pack_bf(g.x - bfr(g.x), g.y - bfr(g.y));
        }
        __syncthreads();

        float acc[2][2][4];
#pragma unroll
        for (int m2 = 0; m2 < 2; ++m2)
#pragma unroll
            for (int n2 = 0; n2 < 2; ++n2)
#pragma unroll
                for (int j = 0; j < 4; ++j) acc[m2][n2][j] = 0.f;

#pragma unroll
        for (int kg = 0; kg < 8; ++kg) {
            u32 Ah[2][4], Al[2][4], Bh[2][2], Bl[2][2];
#pragma unroll
            for (int m2 = 0; m2 < 2; ++m2) {
                int tt = mt * 2 + m2;
#pragma unroll
                for (int r = 0; r < 4; ++r) {
                    int X = (tt * 2 + (r & 1)) & 3;
                    int idx = ((tt * 8 + kg) * 4 + r) * 32 + (lane ^ X);
                    Ah[m2][r] = AFH[idx];
                    Al[m2][r] = AFL[idx];
                }
            }
#pragma unroll
            for (int n2 = 0; n2 < 2; ++n2) {
                int ot = nq * 2 + n2;
#pragma unroll
                for (int r = 0; r < 2; ++r) {
                    int X = ((kg * 2 + r) & 7) << 2;
                    int idx = ((ot * 8 + kg) * 2 + r) * 32 + (lane ^ X);
                    Bh[n2][r] = BFH[idx];
                    Bl[n2][r] = BFL[idx];
                }
            }
#pragma unroll
            for (int m2 = 0; m2 < 2; ++m2)
#pragma unroll
                for (int n2 = 0; n2 < 2; ++n2) {
                    mma16816(acc[m2][n2], Ah[m2], Bh[n2]);
                    mma16816(acc[m2][n2], Ah[m2], Bl[n2]);
                    mma16816(acc[m2][n2], Al[m2], Bh[n2]);
                }
        }

        // epilogue -> Q A-frags / K B-frags / V B-frags (hi/lo) [validated]
#pragma unroll
        for (int m2 = 0; m2 < 2; ++m2)
#pragma unroll
            for (int n2 = 0; n2 < 2; ++n2) {
                int TT = mt * 2 + m2, hh = nq * 2 + n2;
                int o0 = hh * 8 + (tig << 1);
                float b0 = bias[p * 64 + o0], b1 = bias[p * 64 + o0 + 1];
                float v0 = acc[m2][n2][0] + b0, v1 = acc[m2][n2][1] + b1;
                float v2 = acc[m2][n2][2] + b0, v3 = acc[m2][n2][3] + b1;
                if (p == 0) {
                    const float SC = 0.35355339059327373f;
                    v0 *= SC; v1 *= SC; v2 *= SC; v3 *= SC;
                    u32 hi, lo;
                    split2(v0, v1, hi, lo);
                    int i0 = ((hh * 8 + TT) * 2 + 0) * 32 + lane;
                    AQH[i0] = hi; AQL[i0] = lo;
                    split2(v2, v3, hi, lo);
                    int i1 = ((hh * 8 + TT) * 2 + 1) * 32 + lane;
                    AQH[i1] = hi; AQL[i1] = lo;
                } else if (p == 1) {
                    u32 hi, lo;
                    split2(v0, v1, hi, lo);
                    int i0 = (hh * 16 + TT * 2) * 32 + lane;
                    BKH[i0] = hi; BKL[i0] = lo;
                    split2(v2, v3, hi, lo);
                    int i1 = (hh * 16 + TT * 2 + 1) * 32 + lane;
                    BKH[i1] = hi; BKL[i1] = lo;
                } else {
                    char* bh = smc + OF_VBH + hh * 2048 + TT * 256;
                    char* bl = smc + OF_VBL + hh * 2048 + TT * 256;
                    int d0 = tig << 1, d1 = d0 + 1;
                    int wo0 = d0 * 16 + ((gid >> 1) << 2) + ((gid & 1) << 1);
                    int wo1 = d1 * 16 + ((gid >> 1) << 2) + ((gid & 1) << 1);
                    vstore(bh, bl, wo0, v0);
                    vstore(bh, bl, wo1, v1);
                    vstore(bh, bl, 128 + wo0, v2);
                    vstore(bh, bl, 128 + wo1, v3);
                }
            }
        __syncthreads();
    }

    // ---- stage Wo[64][64] as B-fragments (kg 0..3) [validated] ----
    for (int i = tid; i < 2048; i += 512) {
        int o = i >> 5, cp = i & 31;
        float2 g = *(const float2*)(Wo + (o << 6) + (cp << 1));
        int kg = cp >> 3;
        int lane_f = ((o & 7) << 2) + (cp & 3);
        int reg = (cp >> 2) & 1;
        int X = ((cp >> 2) & 7) << 2;
        int idx = ((((o >> 3) << 2) + kg) * 2 + reg) * 32 + (lane_f ^ X);
        BFH[idx] = pack_bf(g.x, g.y);
        BFL[idx] = pack_bf(g.x - bfr(g.x), g.y - bfr(g.y));
    }

    // ---- tensor-core causal attention, kg-outer for 4-way mi ILP ----
    // warp: head h = w&7, half = w>>3 (every SMSP gets halves {0,0,1,1})
    {
        const int h = w & 7, half = w >> 3;
        const bool m0 = (2 * tig) <= gid;
        const bool m1 = (2 * tig + 1) <= gid;

        u32 qh[4][2], ql[4][2];
#pragma unroll
        for (int j = 0; j < 4; ++j) {
            int mi = half + 2 * j;
            qh[j][0] = AQH[((h * 8 + mi) * 2 + 0) * 32 + lane];
            qh[j][1] = AQH[((h * 8 + mi) * 2 + 1) * 32 + lane];
            ql[j][0] = AQL[((h * 8 + mi) * 2 + 0) * 32 + lane];
            ql[j][1] = AQL[((h * 8 + mi) * 2 + 1) * 32 + lane];
        }
        float oa[4][4];
        float l0[4], l1[4];
#pragma unroll
        for (int j = 0; j < 4; ++j) {
            oa[j][0] = oa[j][1] = oa[j][2] = oa[j][3] = 0.f;
            l0[j] = l1[j] = 0.f;
        }

#pragma unroll
        for (int kg = 0; kg < 8; ++kg) {
            u32 kh0 = BKH[(h * 16 + 2 * kg) * 32 + lane];
            u32 kl0 = BKL[(h * 16 + 2 * kg) * 32 + lane];
            u32 kh1 = BKH[(h * 16 + 2 * kg + 1) * 32 + lane];
            u32 kl1 = BKL[(h * 16 + 2 * kg + 1) * 32 + lane];
            u32 vh[2], vl[2];
            vh[0] = VBH[((h * 8 + kg) * 2 + 0) * 32 + lane];
            vh[1] = VBH[((h * 8 + kg) * 2 + 1) * 32 + lane];
            vl[0] = VBL[((h * 8 + kg) * 2 + 0) * 32 + lane];
            vl[1] = VBL[((h * 8 + kg) * 2 + 1) * 32 + lane];

#pragma unroll
            for (int j = 0; j < 4; ++j) {
                if (2 * j + 1 < kg) continue;          // compile-time prune
                int mi = half + 2 * j;
                if (mi < kg) continue;                  // runtime borderline
                bool diag = (mi == kg);

                float s0[4] = {0.f, 0.f, 0.f, 0.f};
                float s1[4] = {0.f, 0.f, 0.f, 0.f};
                mma16808(s0, qh[j], kh0); mma16808(s0, ql[j], kh0); mma16808(s0, qh[j], kl0);
                mma16808(s1, qh[j], kh1); mma16808(s1, ql[j], kh1); mma16808(s1, qh[j], kl1);

                float e00 = __expf(s0[0]), e01 = __expf(s0[1]);
                float e02 = __expf(s0[2]), e03 = __expf(s0[3]);
                float e10 = __expf(s1[0]), e11 = __expf(s1[1]);
                float e12 = __expf(s1[2]), e13 = __expf(s1[3]);
                if (diag) {
                    e00 = m0 ? e00 : 0.f; e01 = m1 ? e01 : 0.f;
                    e10 = 0.f;            e11 = 0.f;
                    e12 = m0 ? e12 : 0.f; e13 = m1 ? e13 : 0.f;
                }
                l0[j] += (e00 + e01) + (e10 + e11);
                l1[j] += (e02 + e03) + (e12 + e13);

                u32 ph[4], pl[4];
                split2(e00, e01, ph[0], pl[0]);
                split2(e02, e03, ph[1], pl[1]);
                split2(e10, e11, ph[2], pl[2]);
                split2(e12, e13, ph[3], pl[3]);

                mma16816(oa[j], ph, vh);
                mma16816(oa[j], pl, vh);
                mma16816(oa[j], ph, vl);
            }
        }

#pragma unroll
        for (int j = 0; j < 4; ++j) {
            int mi = half + 2 * j;
            float L0 = l0[j], L1 = l1[j];
            L0 += __shfl_xor_sync(0xFFFFFFFFu, L0, 1);
            L0 += __shfl_xor_sync(0xFFFFFFFFu, L0, 2);
            L1 += __shfl_xor_sync(0xFFFFFFFFu, L1, 1);
            L1 += __shfl_xor_sync(0xFFFFFFFFu, L1, 2);
            float inv0 = __fdividef(1.f, L0), inv1 = __fdividef(1.f, L1);
            float r0 = oa[j][0] * inv0, r1 = oa[j][1] * inv0;
            float r2 = oa[j][2] * inv1, r3 = oa[j][3] * inv1;

            int kga = h >> 1, regb = (h & 1) << 1;
            int X0 = (mi * 2) & 3, X1 = (mi * 2 + 1) & 3;
            int base = (mi * 4 + kga) * 4;
            u32 hi, lo;
            split2(r0, r1, hi, lo);
            AFH[(base + regb) * 32 + (lane ^ X0)] = hi;
            AFL[(base + regb) * 32 + (lane ^ X0)] = lo;
            split2(r2, r3, hi, lo);
            AFH[(base + regb + 1) * 32 + (lane ^ X1)] = hi;
            AFL[(base + regb + 1) * 32 + (lane ^ X1)] = lo;
        }
    }
    __syncthreads();

    // ---- out projection (kg 0..3) + bias + ReLU -> global [validated] ----
    {
        float acc[2][2][4];
#pragma unroll
        for (int m2 = 0; m2 < 2; ++m2)
#pragma unroll
            for (int n2 = 0; n2 < 2; ++n2)
#pragma unroll
                for (int j = 0; j < 4; ++j) acc[m2][n2][j] = 0.f;

#pragma unroll
        for (int kg = 0; kg < 4; ++kg) {
            u32 Ah[2][4], Al[2][4], Bh[2][2], Bl[2][2];
#pragma unroll
            for (int m2 = 0; m2 < 2; ++m2) {
                int tt = mt * 2 + m2;
#pragma unroll
                for (int r = 0; r < 4; ++r) {
                    int X = (tt * 2 + (r & 1)) & 3;
                    int idx = ((tt * 4 + kg) * 4 + r) * 32 + (lane ^ X);
                    Ah[m2][r] = AFH[idx];
                    Al[m2][r] = AFL[idx];
                }
            }
#pragma unroll
            for (int n2 = 0; n2 < 2; ++n2) {
                int ot = nq * 2 + n2;
#pragma unroll
                for (int r = 0; r < 2; ++r) {
                    int X = ((kg * 2 + r) & 7) << 2;
                    int idx = ((ot * 4 + kg) * 2 + r) * 32 + (lane ^ X);
                    Bh[n2][r] = BFH[idx];
                    Bl[n2][r] = BFL[idx];
                }
            }
#pragma unroll
            for (int m2 = 0; m2 < 2; ++m2)
#pragma unroll
                for (int n2 = 0; n2 < 2; ++n2) {
                    mma16816(acc[m2][n2], Ah[m2], Bh[n2]);
                    mma16816(acc[m2][n2], Ah[m2], Bl[n2]);
                    mma16816(acc[m2][n2], Al[m2], Bh[n2]);
                }
        }

#pragma unroll
        for (int m2 = 0; m2 < 2; ++m2)
#pragma unroll
            for (int n2 = 0; n2 < 2; ++n2) {
                int t0 = ((mt * 2 + m2) << 4) + gid;
                int o0 = ((nq * 2 + n2) << 3) + (tig << 1);
                float b0 = bias[192 + o0], b1 = bias[192 + o0 + 1];
                long base0 = ((long)(b * 64 + o0) * V_ + v) * T_;
                long base1 = base0 + (long)V_ * T_;
                out[base0 + t0]     = fmaxf(acc[m2][n2][0] + b0, 0.f);
                out[base1 + t0]     = fmaxf(acc[m2][n2][1] + b1, 0.f);
                out[base0 + t0 + 8] = fmaxf(acc[m2][n2][2] + b0, 0.f);
                out[base1 + t0 + 8] = fmaxf(acc[m2][n2][3] + b1, 0.f);
            }
    }
}

// ---------------------------------------------------------------------------
extern "C" void kernel_launch(void* const* d_in, const int* in_sizes, int n_in,
                              void* d_out, int out_size)
{
    (void)in_sizes; (void)n_in; (void)out_size;
    const float* x  = (const float*)d_in[0];
    const float* te = (const float*)d_in[1];
    const float* Wq = (const float*)d_in[2];
    const float* bq = (const float*)d_in[3];
    const float* Wk = (const float*)d_in[4];
    const float* bk = (const float*)d_in[5];
    const float* Wv = (const float*)d_in[6];
    const float* bv = (const float*)d_in[7];
    const float* Wo = (const float*)d_in[8];
    const float* bo = (const float*)d_in[9];
    float* out = (float*)d_out;

    cudaFuncSetAttribute(tatt_hmma, cudaFuncAttributeMaxDynamicSharedMemorySize, SMEM_TOTAL);
    tatt_hmma<<<NBLK, 512, SMEM_TOTAL>>>(x, te, Wq, bq, Wk, bk, Wv, bv, Wo, bo, out);
}

// round 9
// speedup vs baseline: 1.5559x; 1.0660x over previous
#include <cuda_runtime.h>
#include <cuda_bf16.h>
#include <cstdint>

typedef unsigned long long u64;
typedef unsigned int       u32;

#define B_   8
#define V_   200
#define T_   128
#define NBLK (B_ * V_)          // 1600

// ---- global scratch: per-block frag arrays (u32[4096] each) ----
__device__ __align__(16) u32 gAQH[NBLK * 4096];
__device__ __align__(16) u32 gAQL[NBLK * 4096];
__device__ __align__(16) u32 gBKH[NBLK * 4096];
__device__ __align__(16) u32 gBKL[NBLK * 4096];
__device__ __align__(16) u32 gVKH[NBLK * 4096];
__device__ __align__(16) u32 gVKL[NBLK * 4096];

// ---- kernel1 smem offsets ----
#define K1_AFH  0
#define K1_AFL  32768
#define K1_BFH  65536
#define K1_BFL  81920
#define K1_BIAS 98304
#define K1_SMEM 99072

// ---- kernel2 smem offsets ----
#define K2_AQH  0            // reused as AO-hi after attention
#define K2_AQL  16384        // reused as AO-lo
#define K2_BKH  32768        // reused: BFoH @32768, BFoL @40960 after attention
#define K2_BKL  49152
#define K2_VBH  65536
#define K2_VBL  81920
#define K2_BIAS 98304
#define K2_SMEM 98560

// ---- helpers ----
__device__ __forceinline__ u32 pack_bf(float a, float b) {
    __nv_bfloat162 h = __floats2bfloat162_rn(a, b);
    u32 r; asm("mov.b32 %0, %1;" : "=r"(r) : "r"(*(u32*)&h)); return r;
}
__device__ __forceinline__ float bfr(float a) {
    return __bfloat162float(__float2bfloat16(a));
}
__device__ __forceinline__ void split2(float a, float b, u32& hi, u32& lo) {
    hi = pack_bf(a, b);
    float ra = __uint_as_float(hi << 16);
    float rb = __uint_as_float(hi & 0xFFFF0000u);
    lo = pack_bf(a - ra, b - rb);
}
__device__ __forceinline__ void mma16816(float* c, const u32* a, const u32* b) {
    asm volatile(
        "mma.sync.aligned.m16n8k16.row.col.f32.bf16.bf16.f32 "
        "{%0,%1,%2,%3}, {%4,%5,%6,%7}, {%8,%9}, {%0,%1,%2,%3};"
        : "+f"(c[0]), "+f"(c[1]), "+f"(c[2]), "+f"(c[3])
        : "r"(a[0]), "r"(a[1]), "r"(a[2]), "r"(a[3]), "r"(b[0]), "r"(b[1]));
}
__device__ __forceinline__ void mma16808(float* c, const u32* a, u32 b) {
    asm volatile(
        "mma.sync.aligned.m16n8k8.row.col.f32.bf16.bf16.f32 "
        "{%0,%1,%2,%3}, {%4,%5}, {%6}, {%0,%1,%2,%3};"
        : "+f"(c[0]), "+f"(c[1]), "+f"(c[2]), "+f"(c[3])
        : "r"(a[0]), "r"(a[1]), "r"(b));
}

extern __shared__ char smc[];

// ===========================================================================
// Kernel 1: concat + QKV projections -> global frag scratch
// 256 threads, 2 CTAs/SM
// ===========================================================================
__global__ __launch_bounds__(256, 2) void tatt_proj(
    const float* __restrict__ x,  const float* __restrict__ tem,
    const float* __restrict__ Wq, const float* __restrict__ bq,
    const float* __restrict__ Wk, const float* __restrict__ bk,
    const float* __restrict__ Wv, const float* __restrict__ bv)
{
    u32*   AFH  = (u32*)(smc + K1_AFH);
    u32*   AFL  = (u32*)(smc + K1_AFL);
    u32*   BFH  = (u32*)(smc + K1_BFH);
    u32*   BFL  = (u32*)(smc + K1_BFL);
    float* bias = (float*)(smc + K1_BIAS);

    const int tid = threadIdx.x, lane = tid & 31, w = tid >> 5;
    const int blk = blockIdx.x, b = blk / V_, v = blk % V_;

    if (tid < 64) {
        bias[tid]       = bq[tid];
        bias[64 + tid]  = bk[tid];
        bias[128 + tid] = bv[tid];
    }

    // ---- stage concat input as A-fragments (hi/lo bf16 split) [validated] ----
    for (int i = tid; i < 8192; i += 256) {
        int cp = i >> 7, t = i & 127;
        int c0 = cp << 1;
        const float* src = (c0 < 64) ? x : tem;
        const float* pb = src + ((long)((b << 6) + (c0 & 63)) * V_ + v) * T_ + t;
        float g0 = pb[0];
        float g1 = pb[(long)V_ * T_];
        int tt = t >> 4, kg = cp >> 3, tin = t & 15;
        int lane_f = ((tin & 7) << 2) + (cp & 3);
        int reg = (tin >> 3) + (((cp >> 2) & 1) << 1);
        int X = (t >> 3) & 3;
        int idx = (((tt << 3) + kg) * 4 + reg) * 32 + (lane_f ^ X);
        AFH[idx] = pack_bf(g0, g1);
        AFL[idx] = pack_bf(g0 - bfr(g0), g1 - bfr(g1));
    }

    const int mt = w >> 1, nq = w & 1;        // 4 x 2 warp grid
    const int gid = lane >> 2, tig = lane & 3;
    const u32 gofs = (u32)blk * 4096u;

    const float* Wsrc[3] = {Wq, Wk, Wv};
#pragma unroll 1
    for (int p = 0; p < 3; ++p) {
        // stage W[o][c] as B-fragments (hi/lo) [validated formulas]
        for (int i = tid; i < 4096; i += 256) {
            int o = i >> 6, cp = i & 63;
            float2 g = *(const float2*)(Wsrc[p] + o * 128 + (cp << 1));
            int kg = cp >> 3;
            int lane_f = ((o & 7) << 2) + (cp & 3);
            int reg = (cp >> 2) & 1;
            int X = ((cp >> 2) & 7) << 2;
            int idx = ((((o >> 3) << 3) + kg) * 2 + reg) * 32 + (lane_f ^ X);
            BFH[idx] = pack_bf(g.x, g.y);
            BFL[idx] = pack_bf(g.x - bfr(g.x), g.y - bfr(g.y));
        }
        __syncthreads();

        float acc[2][4][4];
#pragma unroll
        for (int m2 = 0; m2 < 2; ++m2)
#pragma unroll
            for (int n2 = 0; n2 < 4; ++n2)
#pragma unroll
                for (int j = 0; j < 4; ++j) acc[m2][n2][j] = 0.f;

#pragma unroll
        for (int kg = 0; kg < 8; ++kg) {
            u32 Ah[2][4], Al[2][4], Bh[4][2], Bl[4][2];
#pragma unroll
            for (int m2 = 0; m2 < 2; ++m2) {
                int tt = mt * 2 + m2;
#pragma unroll
                for (int r = 0; r < 4; ++r) {
                    int X = (tt * 2 + (r & 1)) & 3;
                    int idx = ((tt * 8 + kg) * 4 + r) * 32 + (lane ^ X);
                    Ah[m2][r] = AFH[idx];
                    Al[m2][r] = AFL[idx];
                }
            }
#pragma unroll
            for (int n2 = 0; n2 < 4; ++n2) {
                int ot = nq * 4 + n2;
#pragma unroll
                for (int r = 0; r < 2; ++r) {
                    int X = ((kg * 2 + r) & 7) << 2;
                    int idx = ((ot * 8 + kg) * 2 + r) * 32 + (lane ^ X);
                    Bh[n2][r] = BFH[idx];
                    Bl[n2][r] = BFL[idx];
                }
            }
#pragma unroll
            for (int m2 = 0; m2 < 2; ++m2)
#pragma unroll
                for (int n2 = 0; n2 < 4; ++n2) {
                    mma16816(acc[m2][n2], Ah[m2], Bh[n2]);
                    mma16816(acc[m2][n2], Ah[m2], Bl[n2]);
                    mma16816(acc[m2][n2], Al[m2], Bh[n2]);
                }
        }

        // epilogue -> global frag scratch (coalesced u32 stores)
#pragma unroll
        for (int m2 = 0; m2 < 2; ++m2)
#pragma unroll
            for (int n2 = 0; n2 < 4; ++n2) {
                int TT = mt * 2 + m2, hh = nq * 4 + n2;
                int o0 = hh * 8 + (tig << 1);
                float b0 = bias[p * 64 + o0], b1 = bias[p * 64 + o0 + 1];
                float v0 = acc[m2][n2][0] + b0, v1 = acc[m2][n2][1] + b1;
                float v2 = acc[m2][n2][2] + b0, v3 = acc[m2][n2][3] + b1;
                u32 hi, lo;
                if (p == 0) {
                    const float SC = 0.35355339059327373f;
                    v0 *= SC; v1 *= SC; v2 *= SC; v3 *= SC;
                    split2(v0, v1, hi, lo);
                    u32 i0 = gofs + (u32)(((hh * 8 + TT) * 2 + 0) * 32 + lane);
                    gAQH[i0] = hi; gAQL[i0] = lo;
                    split2(v2, v3, hi, lo);
                    u32 i1 = gofs + (u32)(((hh * 8 + TT) * 2 + 1) * 32 + lane);
                    gAQH[i1] = hi; gAQL[i1] = lo;
                } else if (p == 1) {
                    split2(v0, v1, hi, lo);
                    u32 i0 = gofs + (u32)((hh * 16 + TT * 2) * 32 + lane);
                    gBKH[i0] = hi; gBKL[i0] = lo;
                    split2(v2, v3, hi, lo);
                    u32 i1 = gofs + (u32)((hh * 16 + TT * 2 + 1) * 32 + lane);
                    gBKH[i1] = hi; gBKL[i1] = lo;
                } else {
                    split2(v0, v1, hi, lo);
                    u32 i0 = gofs + (u32)((hh * 16 + TT * 2) * 32 + lane);
                    gVKH[i0] = hi; gVKL[i0] = lo;
                    split2(v2, v3, hi, lo);
                    u32 i1 = gofs + (u32)((hh * 16 + TT * 2 + 1) * 32 + lane);
                    gVKH[i1] = hi; gVKL[i1] = lo;
                }
            }
        __syncthreads();
    }
}

// ===========================================================================
// Kernel 2: causal attention (tensor core) + out-proj + ReLU
// 256 threads, 2 CTAs/SM. One warp per head, all 8 mi tiles (36 trips each).
// ===========================================================================
__global__ __launch_bounds__(256, 2) void tatt_attn(
    const float* __restrict__ Wo, const float* __restrict__ bo,
    float* __restrict__ out)
{
    u32*   AQH  = (u32*)(smc + K2_AQH);
    u32*   AQL  = (u32*)(smc + K2_AQL);
    u32*   BKH  = (u32*)(smc + K2_BKH);
    u32*   BKL  = (u32*)(smc + K2_BKL);
    u32*   VBH  = (u32*)(smc + K2_VBH);
    u32*   VBL  = (u32*)(smc + K2_VBL);
    u32*   AOH  = (u32*)(smc + K2_AQH);          // overlays AQ after prologue
    u32*   AOL  = (u32*)(smc + K2_AQL);
    u32*   BOH  = (u32*)(smc + K2_BKH);          // Wo frags, staged post-attention
    u32*   BOL  = (u32*)(smc + K2_BKH + 8192);
    float* bias = (float*)(smc + K2_BIAS);

    const int tid = threadIdx.x, lane = tid & 31, w = tid >> 5;
    const int blk = blockIdx.x, b = blk / V_, v = blk % V_;
    const int gid = lane >> 2, tig = lane & 3;
    const u32 gofs = (u32)blk * 4096u;

    if (tid < 64) bias[tid] = bo[tid];

    // ---- stage Q/K frags: straight uint4 copies (layout-preserving) ----
    {
        const uint4* sQH = (const uint4*)(gAQH + gofs);
        const uint4* sQL = (const uint4*)(gAQL + gofs);
        const uint4* sKH = (const uint4*)(gBKH + gofs);
        const uint4* sKL = (const uint4*)(gBKL + gofs);
        uint4* dQH = (uint4*)AQH; uint4* dQL = (uint4*)AQL;
        uint4* dKH = (uint4*)BKH; uint4* dKL = (uint4*)BKL;
        for (int i = tid; i < 1024; i += 256) {
            dQH[i] = sQH[i]; dQL[i] = sQL[i];
            dKH[i] = sKH[i]; dKL[i] = sKL[i];
        }
    }
    // ---- stage V with transpose: K-layout -> PV B-frag layout ----
    for (int i = tid; i < 4096; i += 256) {
        int lt = i & 31;
        int r  = (i >> 5) & 1;
        int kg = (i >> 6) & 7;
        int h  = i >> 9;
        int tg = lt & 3, gd = lt >> 2;
        u32 sbase = gofs + (u32)((h * 16 + kg * 2 + r) * 32);
        int la = (tg << 3) + (gd >> 1);
        u32 sel = (gd & 1) ? 0x7632u : 0x5410u;
        VBH[i] = __byte_perm(gVKH[sbase + la], gVKH[sbase + la + 4], sel);
        VBL[i] = __byte_perm(gVKL[sbase + la], gVKL[sbase + la + 4], sel);
    }
    __syncthreads();

    // ---- attention: warp w = head h, all mi 0..7 ----
    {
        const int h = w;
        const bool m0 = (2 * tig) <= gid;
        const bool m1 = (2 * tig + 1) <= gid;

        u32 qh[8][2], ql[8][2];
#pragma unroll
        for (int mi = 0; mi < 8; ++mi) {
            qh[mi][0] = AQH[((h * 8 + mi) * 2 + 0) * 32 + lane];
            qh[mi][1] = AQH[((h * 8 + mi) * 2 + 1) * 32 + lane];
            ql[mi][0] = AQL[((h * 8 + mi) * 2 + 0) * 32 + lane];
            ql[mi][1] = AQL[((h * 8 + mi) * 2 + 1) * 32 + lane];
        }
        __syncthreads();     // all Q regs loaded before AO overlays AQ

        float oa[8][4];
        float l0[8], l1[8];
#pragma unroll
        for (int mi = 0; mi < 8; ++mi) {
            oa[mi][0] = oa[mi][1] = oa[mi][2] = oa[mi][3] = 0.f;
            l0[mi] = l1[mi] = 0.f;
        }

#pragma unroll
        for (int kg = 0; kg < 8; ++kg) {
            u32 kh0 = BKH[(h * 16 + 2 * kg) * 32 + lane];
            u32 kl0 = BKL[(h * 16 + 2 * kg) * 32 + lane];
            u32 kh1 = BKH[(h * 16 + 2 * kg + 1) * 32 + lane];
            u32 kl1 = BKL[(h * 16 + 2 * kg + 1) * 32 + lane];
            u32 vh[2], vl[2];
            vh[0] = VBH[((h * 8 + kg) * 2 + 0) * 32 + lane];
            vh[1] = VBH[((h * 8 + kg) * 2 + 1) * 32 + lane];
            vl[0] = VBL[((h * 8 + kg) * 2 + 0) * 32 + lane];
            vl[1] = VBL[((h * 8 + kg) * 2 + 1) * 32 + lane];

#pragma unroll
            for (int mi = 0; mi < 8; ++mi) {
                if (mi < kg) continue;               // compile-time prune
                bool diag = (mi == kg);

                float s0[4] = {0.f, 0.f, 0.f, 0.f};
                float s1[4] = {0.f, 0.f, 0.f, 0.f};
                mma16808(s0, qh[mi], kh0); mma16808(s0, ql[mi], kh0); mma16808(s0, qh[mi], kl0);
                mma16808(s1, qh[mi], kh1); mma16808(s1, ql[mi], kh1); mma16808(s1, qh[mi], kl1);

                float e00 = __expf(s0[0]), e01 = __expf(s0[1]);
                float e02 = __expf(s0[2]), e03 = __expf(s0[3]);
                float e10 = __expf(s1[0]), e11 = __expf(s1[1]);
                float e12 = __expf(s1[2]), e13 = __expf(s1[3]);
                if (diag) {
                    e00 = m0 ? e00 : 0.f; e01 = m1 ? e01 : 0.f;
                    e10 = 0.f;            e11 = 0.f;
                    e12 = m0 ? e12 : 0.f; e13 = m1 ? e13 : 0.f;
                }
                l0[mi] += (e00 + e01) + (e10 + e11);
                l1[mi] += (e02 + e03) + (e12 + e13);

                u32 ph[4], pl[4];
                split2(e00, e01, ph[0], pl[0]);
                split2(e02, e03, ph[1], pl[1]);
                split2(e10, e11, ph[2], pl[2]);
                split2(e12, e13, ph[3], pl[3]);

                mma16816(oa[mi], ph, vh);
                mma16816(oa[mi], pl, vh);
                mma16816(oa[mi], ph, vl);
            }
        }

#pragma unroll
        for (int mi = 0; mi < 8; ++mi) {
            float L0 = l0[mi], L1 = l1[mi];
            L0 += __shfl_xor_sync(0xFFFFFFFFu, L0, 1);
            L0 += __shfl_xor_sync(0xFFFFFFFFu, L0, 2);
            L1 += __shfl_xor_sync(0xFFFFFFFFu, L1, 1);
            L1 += __shfl_xor_sync(0xFFFFFFFFu, L1, 2);
            float inv0 = __fdividef(1.f, L0), inv1 = __fdividef(1.f, L1);
            float r0 = oa[mi][0] * inv0, r1 = oa[mi][1] * inv0;
            float r2 = oa[mi][2] * inv1, r3 = oa[mi][3] * inv1;

            int kga = h >> 1, regb = (h & 1) << 1;
            int X0 = (mi * 2) & 3, X1 = (mi * 2 + 1) & 3;
            int base = (mi * 4 + kga) * 4;
            u32 hi, lo;
            split2(r0, r1, hi, lo);
            AOH[(base + regb) * 32 + (lane ^ X0)] = hi;
            AOL[(base + regb) * 32 + (lane ^ X0)] = lo;
            split2(r2, r3, hi, lo);
            AOH[(base + regb + 1) * 32 + (lane ^ X1)] = hi;
            AOL[(base + regb + 1) * 32 + (lane ^ X1)] = lo;
        }
    }
    __syncthreads();

    // ---- stage Wo[64][64] as B-fragments (kg 0..3) [validated formulas] ----
    for (int i = tid; i < 2048; i += 256) {
        int o = i >> 5, cp = i & 31;
        float2 g = *(const float2*)(Wo + (o << 6) + (cp << 1));
        int kg = cp >> 3;
        int lane_f = ((o & 7) << 2) + (cp & 3);
        int reg = (cp >> 2) & 1;
        int X = ((cp >> 2) & 7) << 2;
        int idx = ((((o >> 3) << 2) + kg) * 2 + reg) * 32 + (lane_f ^ X);
        BOH[idx] = pack_bf(g.x, g.y);
        BOL[idx] = pack_bf(g.x - bfr(g.x), g.y - bfr(g.y));
    }
    __syncthreads();

    // ---- out projection + bias + ReLU -> global ----
    {
        const int mt = w >> 1, nq = w & 1;
        float acc[2][4][4];
#pragma unroll
        for (int m2 = 0; m2 < 2; ++m2)
#pragma unroll
            for (int n2 = 0; n2 < 4; ++n2)
#pragma unroll
                for (int j = 0; j < 4; ++j) acc[m2][n2][j] = 0.f;

#pragma unroll
        for (int kg = 0; kg < 4; ++kg) {
            u32 Ah[2][4], Al[2][4], Bh[4][2], Bl[4][2];
#pragma unroll
            for (int m2 = 0; m2 < 2; ++m2) {
                int tt = mt * 2 + m2;
#pragma unroll
                for (int r = 0; r < 4; ++r) {
                    int X = (tt * 2 + (r & 1)) & 3;
                    int idx = ((tt * 4 + kg) * 4 + r) * 32 + (lane ^ X);
                    Ah[m2][r] = AOH[idx];
                    Al[m2][r] = AOL[idx];
                }
            }
#pragma unroll
            for (int n2 = 0; n2 < 4; ++n2) {
                int ot = nq * 4 + n2;
#pragma unroll
                for (int r = 0; r < 2; ++r) {
                    int X = ((kg * 2 + r) & 7) << 2;
                    int idx = ((ot * 4 + kg) * 2 + r) * 32 + (lane ^ X);
                    Bh[n2][r] = BOH[idx];
                    Bl[n2][r] = BOL[idx];
                }
            }
#pragma unroll
            for (int m2 = 0; m2 < 2; ++m2)
#pragma unroll
                for (int n2 = 0; n2 < 4; ++n2) {
                    mma16816(acc[m2][n2], Ah[m2], Bh[n2]);
                    mma16816(acc[m2][n2], Ah[m2], Bl[n2]);
                    mma16816(acc[m2][n2], Al[m2], Bh[n2]);
                }
        }

#pragma unroll
        for (int m2 = 0; m2 < 2; ++m2)
#pragma unroll
            for (int n2 = 0; n2 < 4; ++n2) {
                int t0 = ((mt * 2 + m2) << 4) + gid;
                int o0 = ((nq * 4 + n2) << 3) + (tig << 1);
                float b0 = bias[o0], b1 = bias[o0 + 1];
                long base0 = ((long)(b * 64 + o0) * V_ + v) * T_;
                long base1 = base0 + (long)V_ * T_;
                out[base0 + t0]     = fmaxf(acc[m2][n2][0] + b0, 0.f);
                out[base1 + t0]     = fmaxf(acc[m2][n2][1] + b1, 0.f);
                out[base0 + t0 + 8] = fmaxf(acc[m2][n2][2] + b0, 0.f);
                out[base1 + t0 + 8] = fmaxf(acc[m2][n2][3] + b1, 0.f);
            }
    }
}

// ---------------------------------------------------------------------------
extern "C" void kernel_launch(void* const* d_in, const int* in_sizes, int n_in,
                              void* d_out, int out_size)
{
    (void)in_sizes; (void)n_in; (void)out_size;
    const float* x  = (const float*)d_in[0];
    const float* te = (const float*)d_in[1];
    const float* Wq = (const float*)d_in[2];
    const float* bq = (const float*)d_in[3];
    const float* Wk = (const float*)d_in[4];
    const float* bk = (const float*)d_in[5];
    const float* Wv = (const float*)d_in[6];
    const float* bv = (const float*)d_in[7];
    const float* Wo = (const float*)d_in[8];
    const float* bo = (const float*)d_in[9];
    float* out = (float*)d_out;

    cudaFuncSetAttribute(tatt_proj, cudaFuncAttributeMaxDynamicSharedMemorySize, K1_SMEM);
    cudaFuncSetAttribute(tatt_attn, cudaFuncAttributeMaxDynamicSharedMemorySize, K2_SMEM);

    tatt_proj<<<NBLK, 256, K1_SMEM>>>(x, te, Wq, bq, Wk, bk, Wv, bv);
    tatt_attn<<<NBLK, 256, K2_SMEM>>>(Wo, bo, out);
}

// round 10
// speedup vs baseline: 1.7364x; 1.1160x over previous
#include <cuda_runtime.h>
#include <cuda_bf16.h>
#include <cstdint>

typedef unsigned long long u64;
typedef unsigned int       u32;

#define B_   8
#define V_   200
#define T_   128
#define NBLK (B_ * V_)          // 1600

// ---- global scratch: per-block frag arrays (u32[4096] each) ----
__device__ __align__(16) u32 gAQH[NBLK * 4096];
__device__ __align__(16) u32 gAQL[NBLK * 4096];
__device__ __align__(16) u32 gBKH[NBLK * 4096];
__device__ __align__(16) u32 gBKL[NBLK * 4096];
__device__ __align__(16) u32 gVKH[NBLK * 4096];
__device__ __align__(16) u32 gVKL[NBLK * 4096];
// ---- pre-fragmented weights (written once by prep_w) ----
__device__ __align__(16) u32 gWBH[3 * 4096];
__device__ __align__(16) u32 gWBL[3 * 4096];
__device__ __align__(16) u32 gWOH[2048];
__device__ __align__(16) u32 gWOL[2048];

// ---- kernel1 smem ----
#define K1_AFH  0
#define K1_AFL  32768
#define K1_SMEM 65536
// ---- kernel2 smem ----
#define K2_BKH  0            // AOH overlays after attention
#define K2_BKL  16384        // AOL overlays after attention
#define K2_VBH  32768
#define K2_VBL  49152
#define K2_SMEM 65536

// ---- helpers ----
__device__ __forceinline__ u32 pack_bf(float a, float b) {
    __nv_bfloat162 h = __floats2bfloat162_rn(a, b);
    u32 r; asm("mov.b32 %0, %1;" : "=r"(r) : "r"(*(u32*)&h)); return r;
}
__device__ __forceinline__ float bfr(float a) {
    return __bfloat162float(__float2bfloat16(a));
}
__device__ __forceinline__ void split2(float a, float b, u32& hi, u32& lo) {
    hi = pack_bf(a, b);
    float ra = __uint_as_float(hi << 16);
    float rb = __uint_as_float(hi & 0xFFFF0000u);
    lo = pack_bf(a - ra, b - rb);
}
__device__ __forceinline__ float ex2f(float x) {
    float y; asm("ex2.approx.f32 %0, %1;" : "=f"(y) : "f"(x)); return y;
}
__device__ __forceinline__ void mma16816(float* c, const u32* a, const u32* b) {
    asm volatile(
        "mma.sync.aligned.m16n8k16.row.col.f32.bf16.bf16.f32 "
        "{%0,%1,%2,%3}, {%4,%5,%6,%7}, {%8,%9}, {%0,%1,%2,%3};"
        : "+f"(c[0]), "+f"(c[1]), "+f"(c[2]), "+f"(c[3])
        : "r"(a[0]), "r"(a[1]), "r"(a[2]), "r"(a[3]), "r"(b[0]), "r"(b[1]));
}
__device__ __forceinline__ void mma16808(float* c, const u32* a, u32 b) {
    asm volatile(
        "mma.sync.aligned.m16n8k8.row.col.f32.bf16.bf16.f32 "
        "{%0,%1,%2,%3}, {%4,%5}, {%6}, {%0,%1,%2,%3};"
        : "+f"(c[0]), "+f"(c[1]), "+f"(c[2]), "+f"(c[3])
        : "r"(a[0]), "r"(a[1]), "r"(b));
}

extern __shared__ char smc[];

// ===========================================================================
// Kernel 0: pre-fragment weights into global tables (validated formulas)
// ===========================================================================
__global__ void prep_w(const float* __restrict__ Wq, const float* __restrict__ Wk,
                       const float* __restrict__ Wv, const float* __restrict__ Wo)
{
    const int p = blockIdx.x, tid = threadIdx.x;
    if (p < 3) {
        const float* W = (p == 0) ? Wq : (p == 1 ? Wk : Wv);
        for (int i = tid; i < 4096; i += 256) {
            int o = i >> 6, cp = i & 63;
            float2 g = *(const float2*)(W + o * 128 + (cp << 1));
            int kg = cp >> 3;
            int lane_f = ((o & 7) << 2) + (cp & 3);
            int reg = (cp >> 2) & 1;
            int X = ((cp >> 2) & 7) << 2;
            int idx = ((((o >> 3) << 3) + kg) * 2 + reg) * 32 + (lane_f ^ X);
            gWBH[p * 4096 + idx] = pack_bf(g.x, g.y);
            gWBL[p * 4096 + idx] = pack_bf(g.x - bfr(g.x), g.y - bfr(g.y));
        }
    } else {
        for (int i = tid; i < 2048; i += 256) {
            int o = i >> 5, cp = i & 31;
            float2 g = *(const float2*)(Wo + (o << 6) + (cp << 1));
            int kg = cp >> 3;
            int lane_f = ((o & 7) << 2) + (cp & 3);
            int reg = (cp >> 2) & 1;
            int X = ((cp >> 2) & 7) << 2;
            int idx = ((((o >> 3) << 2) + kg) * 2 + reg) * 32 + (lane_f ^ X);
            gWOH[idx] = pack_bf(g.x, g.y);
            gWOL[idx] = pack_bf(g.x - bfr(g.x), g.y - bfr(g.y));
        }
    }
}

// ===========================================================================
// Kernel 1: concat + QKV projections -> global frag scratch
// 256 threads, 2 CTAs/SM. B-fragments read directly from gWB tables (L2).
// ===========================================================================
__global__ __launch_bounds__(256, 2) void tatt_proj(
    const float* __restrict__ x,  const float* __restrict__ tem,
    const float* __restrict__ bq, const float* __restrict__ bk,
    const float* __restrict__ bv)
{
    u32* AFH = (u32*)(smc + K1_AFH);
    u32* AFL = (u32*)(smc + K1_AFL);

    const int tid = threadIdx.x, lane = tid & 31, w = tid >> 5;
    const int blk = blockIdx.x, b = blk / V_, v = blk % V_;

    // ---- stage concat input as A-fragments (hi/lo bf16 split) [validated] ----
    for (int i = tid; i < 8192; i += 256) {
        int cp = i >> 7, t = i & 127;
        int c0 = cp << 1;
        const float* src = (c0 < 64) ? x : tem;
        const float* pb = src + ((long)((b << 6) + (c0 & 63)) * V_ + v) * T_ + t;
        float g0 = pb[0];
        float g1 = pb[(long)V_ * T_];
        int tt = t >> 4, kg = cp >> 3, tin = t & 15;
        int lane_f = ((tin & 7) << 2) + (cp & 3);
        int reg = (tin >> 3) + (((cp >> 2) & 1) << 1);
        int X = (t >> 3) & 3;
        int idx = (((tt << 3) + kg) * 4 + reg) * 32 + (lane_f ^ X);
        AFH[idx] = pack_bf(g0, g1);
        AFL[idx] = pack_bf(g0 - bfr(g0), g1 - bfr(g1));
    }
    __syncthreads();

    const int mt = w >> 1, nq = w & 1;        // 4 x 2 warp grid
    const int gid = lane >> 2, tig = lane & 3;
    const u32 gofs = (u32)blk * 4096u;
    const float* bsrc[3] = {bq, bk, bv};

#pragma unroll 1
    for (int p = 0; p < 3; ++p) {
        const u32* WBH = gWBH + p * 4096;
        const u32* WBL = gWBL + p * 4096;

        float acc[2][4][4];
#pragma unroll
        for (int m2 = 0; m2 < 2; ++m2)
#pragma unroll
            for (int n2 = 0; n2 < 4; ++n2)
#pragma unroll
                for (int j = 0; j < 4; ++j) acc[m2][n2][j] = 0.f;

#pragma unroll
        for (int kg = 0; kg < 8; ++kg) {
            u32 Ah[2][4], Al[2][4], Bh[4][2], Bl[4][2];
#pragma unroll
            for (int m2 = 0; m2 < 2; ++m2) {
                int tt = mt * 2 + m2;
#pragma unroll
                for (int r = 0; r < 4; ++r) {
                    int X = (tt * 2 + (r & 1)) & 3;
                    int idx = ((tt * 8 + kg) * 4 + r) * 32 + (lane ^ X);
                    Ah[m2][r] = AFH[idx];
                    Al[m2][r] = AFL[idx];
                }
            }
#pragma unroll
            for (int n2 = 0; n2 < 4; ++n2) {
                int ot = nq * 4 + n2;
#pragma unroll
                for (int r = 0; r < 2; ++r) {
                    int X = ((kg * 2 + r) & 7) << 2;
                    int idx = ((ot * 8 + kg) * 2 + r) * 32 + (lane ^ X);
                    Bh[n2][r] = WBH[idx];
                    Bl[n2][r] = WBL[idx];
                }
            }
#pragma unroll
            for (int m2 = 0; m2 < 2; ++m2)
#pragma unroll
                for (int n2 = 0; n2 < 4; ++n2) {
                    mma16816(acc[m2][n2], Ah[m2], Bh[n2]);
                    mma16816(acc[m2][n2], Ah[m2], Bl[n2]);
                    mma16816(acc[m2][n2], Al[m2], Bh[n2]);
                }
        }

        // epilogue -> global frag scratch (coalesced u32 stores)
#pragma unroll
        for (int m2 = 0; m2 < 2; ++m2)
#pragma unroll
            for (int n2 = 0; n2 < 4; ++n2) {
                int TT = mt * 2 + m2, hh = nq * 4 + n2;
                int o0 = hh * 8 + (tig << 1);
                float b0 = bsrc[p][o0], b1 = bsrc[p][o0 + 1];
                float v0 = acc[m2][n2][0] + b0, v1 = acc[m2][n2][1] + b1;
                float v2 = acc[m2][n2][2] + b0, v3 = acc[m2][n2][3] + b1;
                u32 hi, lo;
                if (p == 0) {
                    const float SC = 0.5101344248f;    // 1/sqrt(8) * log2(e)
                    v0 *= SC; v1 *= SC; v2 *= SC; v3 *= SC;
                    split2(v0, v1, hi, lo);
                    u32 i0 = gofs + (u32)(((hh * 8 + TT) * 2 + 0) * 32 + lane);
                    gAQH[i0] = hi; gAQL[i0] = lo;
                    split2(v2, v3, hi, lo);
                    u32 i1 = gofs + (u32)(((hh * 8 + TT) * 2 + 1) * 32 + lane);
                    gAQH[i1] = hi; gAQL[i1] = lo;
                } else if (p == 1) {
                    split2(v0, v1, hi, lo);
                    u32 i0 = gofs + (u32)((hh * 16 + TT * 2) * 32 + lane);
                    gBKH[i0] = hi; gBKL[i0] = lo;
                    split2(v2, v3, hi, lo);
                    u32 i1 = gofs + (u32)((hh * 16 + TT * 2 + 1) * 32 + lane);
                    gBKH[i1] = hi; gBKL[i1] = lo;
                } else {
                    split2(v0, v1, hi, lo);
                    u32 i0 = gofs + (u32)((hh * 16 + TT * 2) * 32 + lane);
                    gVKH[i0] = hi; gVKL[i0] = lo;
                    split2(v2, v3, hi, lo);
                    u32 i1 = gofs + (u32)((hh * 16 + TT * 2 + 1) * 32 + lane);
                    gVKH[i1] = hi; gVKL[i1] = lo;
                }
            }
    }
}

// ===========================================================================
// Kernel 2: causal attention (tensor core) + out-proj + ReLU
// 256 threads, 2 CTAs/SM. Q frags direct from global; AO overlays K region.
// ===========================================================================
__global__ __launch_bounds__(256, 2) void tatt_attn(
    const float* __restrict__ bo, float* __restrict__ out)
{
    u32* BKH = (u32*)(smc + K2_BKH);
    u32* BKL = (u32*)(smc + K2_BKL);
    u32* VBH = (u32*)(smc + K2_VBH);
    u32* VBL = (u32*)(smc + K2_VBL);
    u32* AOH = (u32*)(smc + K2_BKH);   // overlays K after post-attention barrier
    u32* AOL = (u32*)(smc + K2_BKL);

    const int tid = threadIdx.x, lane = tid & 31, w = tid >> 5;
    const int blk = blockIdx.x, b = blk / V_, v = blk % V_;
    const int gid = lane >> 2, tig = lane & 3;
    const u32 gofs = (u32)blk * 4096u;

    // ---- stage K frags: straight uint4 copies ----
    {
        const uint4* sKH = (const uint4*)(gBKH + gofs);
        const uint4* sKL = (const uint4*)(gBKL + gofs);
        uint4* dKH = (uint4*)BKH; uint4* dKL = (uint4*)BKL;
        for (int i = tid; i < 1024; i += 256) { dKH[i] = sKH[i]; dKL[i] = sKL[i]; }
    }
    // ---- stage V with transpose: K-layout -> PV B-frag layout ----
    for (int i = tid; i < 4096; i += 256) {
        int lt = i & 31;
        int r  = (i >> 5) & 1;
        int kg = (i >> 6) & 7;
        int h  = i >> 9;
        int tg = lt & 3, gd = lt >> 2;
        u32 sbase = gofs + (u32)((h * 16 + kg * 2 + r) * 32);
        int la = (tg << 3) + (gd >> 1);
        u32 sel = (gd & 1) ? 0x7632u : 0x5410u;
        VBH[i] = __byte_perm(gVKH[sbase + la], gVKH[sbase + la + 4], sel);
        VBL[i] = __byte_perm(gVKL[sbase + la], gVKL[sbase + la + 4], sel);
    }
    __syncthreads();

    // ---- attention: warp w = head h, all mi 0..7 ----
    float oa[8][4];
    float l0[8], l1[8];
    {
        const int h = w;
        const bool m0 = (2 * tig) <= gid;
        const bool m1 = (2 * tig + 1) <= gid;

        u32 qh[8][2], ql[8][2];
#pragma unroll
        for (int mi = 0; mi < 8; ++mi) {
            qh[mi][0] = gAQH[gofs + ((h * 8 + mi) * 2 + 0) * 32 + lane];
            qh[mi][1] = gAQH[gofs + ((h * 8 + mi) * 2 + 1) * 32 + lane];
            ql[mi][0] = gAQL[gofs + ((h * 8 + mi) * 2 + 0) * 32 + lane];
            ql[mi][1] = gAQL[gofs + ((h * 8 + mi) * 2 + 1) * 32 + lane];
        }
#pragma unroll
        for (int mi = 0; mi < 8; ++mi) {
            oa[mi][0] = oa[mi][1] = oa[mi][2] = oa[mi][3] = 0.f;
            l0[mi] = l1[mi] = 0.f;
        }

#pragma unroll
        for (int kg = 0; kg < 8; ++kg) {
            u32 kh0 = BKH[(h * 16 + 2 * kg) * 32 + lane];
            u32 kl0 = BKL[(h * 16 + 2 * kg) * 32 + lane];
            u32 kh1 = BKH[(h * 16 + 2 * kg + 1) * 32 + lane];
            u32 kl1 = BKL[(h * 16 + 2 * kg + 1) * 32 + lane];
            u32 vh[2], vl[2];
            vh[0] = VBH[((h * 8 + kg) * 2 + 0) * 32 + lane];
            vh[1] = VBH[((h * 8 + kg) * 2 + 1) * 32 + lane];
            vl[0] = VBL[((h * 8 + kg) * 2 + 0) * 32 + lane];
            vl[1] = VBL[((h * 8 + kg) * 2 + 1) * 32 + lane];

#pragma unroll
            for (int mi = 0; mi < 8; ++mi) {
                if (mi < kg) continue;               // compile-time prune
                bool diag = (mi == kg);

                float s0[4] = {0.f, 0.f, 0.f, 0.f};
                float s1[4] = {0.f, 0.f, 0.f, 0.f};
                mma16808(s0, qh[mi], kh0); mma16808(s0, ql[mi], kh0); mma16808(s0, qh[mi], kl0);
                mma16808(s1, qh[mi], kh1); mma16808(s1, ql[mi], kh1); mma16808(s1, qh[mi], kl1);

                float e00 = ex2f(s0[0]), e01 = ex2f(s0[1]);
                float e02 = ex2f(s0[2]), e03 = ex2f(s0[3]);
                float e10 = ex2f(s1[0]), e11 = ex2f(s1[1]);
                float e12 = ex2f(s1[2]), e13 = ex2f(s1[3]);
                if (diag) {
                    e00 = m0 ? e00 : 0.f; e01 = m1 ? e01 : 0.f;
                    e10 = 0.f;            e11 = 0.f;
                    e12 = m0 ? e12 : 0.f; e13 = m1 ? e13 : 0.f;
                }
                l0[mi] += (e00 + e01) + (e10 + e11);
                l1[mi] += (e02 + e03) + (e12 + e13);

                u32 ph[4], pl[4];
                split2(e00, e01, ph[0], pl[0]);
                split2(e02, e03, ph[1], pl[1]);
                split2(e10, e11, ph[2], pl[2]);
                split2(e12, e13, ph[3], pl[3]);

                mma16816(oa[mi], ph, vh);
                mma16816(oa[mi], pl, vh);
                mma16816(oa[mi], ph, vl);
            }
        }
    }
    __syncthreads();          // all warps done reading BK/VB

    // ---- normalize + write AO frags (overlay K region) ----
    {
        const int h = w;
#pragma unroll
        for (int mi = 0; mi < 8; ++mi) {
            float L0 = l0[mi], L1 = l1[mi];
            L0 += __shfl_xor_sync(0xFFFFFFFFu, L0, 1);
            L0 += __shfl_xor_sync(0xFFFFFFFFu, L0, 2);
            L1 += __shfl_xor_sync(0xFFFFFFFFu, L1, 1);
            L1 += __shfl_xor_sync(0xFFFFFFFFu, L1, 2);
            float inv0 = __fdividef(1.f, L0), inv1 = __fdividef(1.f, L1);
            float r0 = oa[mi][0] * inv0, r1 = oa[mi][1] * inv0;
            float r2 = oa[mi][2] * inv1, r3 = oa[mi][3] * inv1;

            int kga = h >> 1, regb = (h & 1) << 1;
            int X0 = (mi * 2) & 3, X1 = (mi * 2 + 1) & 3;
            int base = (mi * 4 + kga) * 4;
            u32 hi, lo;
            split2(r0, r1, hi, lo);
            AOH[(base + regb) * 32 + (lane ^ X0)] = hi;
            AOL[(base + regb) * 32 + (lane ^ X0)] = lo;
            split2(r2, r3, hi, lo);
            AOH[(base + regb + 1) * 32 + (lane ^ X1)] = hi;
            AOL[(base + regb + 1) * 32 + (lane ^ X1)] = lo;
        }
    }
    __syncthreads();

    // ---- out projection + bias + ReLU -> global (B from gWO tables) ----
    {
        const int mt = w >> 1, nq = w & 1;
        float acc[2][4][4];
#pragma unroll
        for (int m2 = 0; m2 < 2; ++m2)
#pragma unroll
            for (int n2 = 0; n2 < 4; ++n2)
#pragma unroll
                for (int j = 0; j < 4; ++j) acc[m2][n2][j] = 0.f;

#pragma unroll
        for (int kg = 0; kg < 4; ++kg) {
            u32 Ah[2][4], Al[2][4], Bh[4][2], Bl[4][2];
#pragma unroll
            for (int m2 = 0; m2 < 2; ++m2) {
                int tt = mt * 2 + m2;
#pragma unroll
                for (int r = 0; r < 4; ++r) {
                    int X = (tt * 2 + (r & 1)) & 3;
                    int idx = ((tt * 4 + kg) * 4 + r) * 32 + (lane ^ X);
                    Ah[m2][r] = AOH[idx];
                    Al[m2][r] = AOL[idx];
                }
            }
#pragma unroll
            for (int n2 = 0; n2 < 4; ++n2) {
                int ot = nq * 4 + n2;
#pragma unroll
                for (int r = 0; r < 2; ++r) {
                    int X = ((kg * 2 + r) & 7) << 2;
                    int idx = ((ot * 4 + kg) * 2 + r) * 32 + (lane ^ X);
                    Bh[n2][r] = gWOH[idx];
                    Bl[n2][r] = gWOL[idx];
                }
            }
#pragma unroll
            for (int m2 = 0; m2 < 2; ++m2)
#pragma unroll
                for (int n2 = 0; n2 < 4; ++n2) {
                    mma16816(acc[m2][n2], Ah[m2], Bh[n2]);
                    mma16816(acc[m2][n2], Ah[m2], Bl[n2]);
                    mma16816(acc[m2][n2], Al[m2], Bh[n2]);
                }
        }

#pragma unroll
        for (int m2 = 0; m2 < 2; ++m2)
#pragma unroll
            for (int n2 = 0; n2 < 4; ++n2) {
                int t0 = ((mt * 2 + m2) << 4) + gid;
                int o0 = ((nq * 4 + n2) << 3) + (tig << 1);
                float b0 = bo[o0], b1 = bo[o0 + 1];
                long base0 = ((long)(b * 64 + o0) * V_ + v) * T_;
                long base1 = base0 + (long)V_ * T_;
                out[base0 + t0]     = fmaxf(acc[m2][n2][0] + b0, 0.f);
                out[base1 + t0]     = fmaxf(acc[m2][n2][1] + b1, 0.f);
                out[base0 + t0 + 8] = fmaxf(acc[m2][n2][2] + b0, 0.f);
                out[base1 + t0 + 8] = fmaxf(acc[m2][n2][3] + b1, 0.f);
            }
    }
}

// ---------------------------------------------------------------------------
extern "C" void kernel_launch(void* const* d_in, const int* in_sizes, int n_in,
                              void* d_out, int out_size)
{
    (void)in_sizes; (void)n_in; (void)out_size;
    const float* x  = (const float*)d_in[0];
    const float* te = (const float*)d_in[1];
    const float* Wq = (const float*)d_in[2];
    const float* bq = (const float*)d_in[3];
    const float* Wk = (const float*)d_in[4];
    const float* bk = (const float*)d_in[5];
    const float* Wv = (const float*)d_in[6];
    const float* bv = (const float*)d_in[7];
    const float* Wo = (const float*)d_in[8];
    const float* bo = (const float*)d_in[9];
    float* out = (float*)d_out;

    cudaFuncSetAttribute(tatt_proj, cudaFuncAttributeMaxDynamicSharedMemorySize, K1_SMEM);
    cudaFuncSetAttribute(tatt_attn, cudaFuncAttributeMaxDynamicSharedMemorySize, K2_SMEM);

    prep_w<<<4, 256>>>(Wq, Wk, Wv, Wo);
    tatt_proj<<<NBLK, 256, K1_SMEM>>>(x, te, bq, bk, bv);
    tatt_attn<<<NBLK, 256, K2_SMEM>>>(bo, out);
}

// round 11
// speedup vs baseline: 2.4643x; 1.4192x over previous
#include <cuda_runtime.h>
#include <cuda_bf16.h>
#include <cstdint>

typedef unsigned long long u64;
typedef unsigned int       u32;

#define B_   8
#define V_   200
#define T_   128
#define NBLK (B_ * V_)          // 1600

// ---- global scratch: Q frags per block + pre-fragmented weights ----
__device__ __align__(16) u32 gAQH[NBLK * 4096];
__device__ __align__(16) u32 gAQL[NBLK * 4096];
__device__ __align__(16) u32 gWBH[3 * 4096];
__device__ __align__(16) u32 gWBL[3 * 4096];
__device__ __align__(16) u32 gWOH[2048];
__device__ __align__(16) u32 gWOL[2048];

// ---- fused-kernel smem (bytes) ----
// [0,32768)      AFH  (overlay after p=2: VBH @0, VBL @16384)
// [32768,65536)  AFL  (overlay after attention: AOH @32768, AOL @49152)
// [65536,81920)  BKH
// [81920,98304)  BKL
#define SM_AFH  0
#define SM_AFL  32768
#define SM_VBH  0
#define SM_VBL  16384
#define SM_AOH  32768
#define SM_AOL  49152
#define SM_BKH  65536
#define SM_BKL  81920
#define SMEM_TOTAL 98304

// ---- helpers ----
__device__ __forceinline__ u32 pack_bf(float a, float b) {
    __nv_bfloat162 h = __floats2bfloat162_rn(a, b);
    u32 r; asm("mov.b32 %0, %1;" : "=r"(r) : "r"(*(u32*)&h)); return r;
}
__device__ __forceinline__ float bfr(float a) {
    return __bfloat162float(__float2bfloat16(a));
}
__device__ __forceinline__ void split2(float a, float b, u32& hi, u32& lo) {
    hi = pack_bf(a, b);
    float ra = __uint_as_float(hi << 16);
    float rb = __uint_as_float(hi & 0xFFFF0000u);
    lo = pack_bf(a - ra, b - rb);
}
__device__ __forceinline__ float ex2f(float x) {
    float y; asm("ex2.approx.f32 %0, %1;" : "=f"(y) : "f"(x)); return y;
}
__device__ __forceinline__ void mma16816(float* c, const u32* a, const u32* b) {
    asm volatile(
        "mma.sync.aligned.m16n8k16.row.col.f32.bf16.bf16.f32 "
        "{%0,%1,%2,%3}, {%4,%5,%6,%7}, {%8,%9}, {%0,%1,%2,%3};"
        : "+f"(c[0]), "+f"(c[1]), "+f"(c[2]), "+f"(c[3])
        : "r"(a[0]), "r"(a[1]), "r"(a[2]), "r"(a[3]), "r"(b[0]), "r"(b[1]));
}
__device__ __forceinline__ void mma16808(float* c, const u32* a, u32 b) {
    asm volatile(
        "mma.sync.aligned.m16n8k8.row.col.f32.bf16.bf16.f32 "
        "{%0,%1,%2,%3}, {%4,%5}, {%6}, {%0,%1,%2,%3};"
        : "+f"(c[0]), "+f"(c[1]), "+f"(c[2]), "+f"(c[3])
        : "r"(a[0]), "r"(a[1]), "r"(b));
}
__device__ __forceinline__ void vstore(char* bh, char* bl, int off, float v) {
    __nv_bfloat16 h = __float2bfloat16(v);
    *(__nv_bfloat16*)(bh + off) = h;
    *(__nv_bfloat16*)(bl + off) = __float2bfloat16(v - __bfloat162float(h));
}

extern __shared__ char smc[];

// ===========================================================================
// Kernel 0: pre-fragment weights into global tables (validated formulas)
// ===========================================================================
__global__ void prep_w(const float* __restrict__ Wq, const float* __restrict__ Wk,
                       const float* __restrict__ Wv, const float* __restrict__ Wo)
{
    const int p = blockIdx.x, tid = threadIdx.x;
    if (p < 3) {
        const float* W = (p == 0) ? Wq : (p == 1 ? Wk : Wv);
        for (int i = tid; i < 4096; i += 1024) {
            int o = i >> 6, cp = i & 63;
            float2 g = *(const float2*)(W + o * 128 + (cp << 1));
            int kg = cp >> 3;
            int lane_f = ((o & 7) << 2) + (cp & 3);
            int reg = (cp >> 2) & 1;
            int X = ((cp >> 2) & 7) << 2;
            int idx = ((((o >> 3) << 3) + kg) * 2 + reg) * 32 + (lane_f ^ X);
            gWBH[p * 4096 + idx] = pack_bf(g.x, g.y);
            gWBL[p * 4096 + idx] = pack_bf(g.x - bfr(g.x), g.y - bfr(g.y));
        }
    } else {
        for (int i = tid; i < 2048; i += 1024) {
            int o = i >> 5, cp = i & 31;
            float2 g = *(const float2*)(Wo + (o << 6) + (cp << 1));
            int kg = cp >> 3;
            int lane_f = ((o & 7) << 2) + (cp & 3);
            int reg = (cp >> 2) & 1;
            int X = ((cp >> 2) & 7) << 2;
            int idx = ((((o >> 3) << 2) + kg) * 2 + reg) * 32 + (lane_f ^ X);
            gWOH[idx] = pack_bf(g.x, g.y);
            gWOL[idx] = pack_bf(g.x - bfr(g.x), g.y - bfr(g.y));
        }
    }
}

// ===========================================================================
// Fused kernel: concat + QKV proj + causal attention + out-proj + ReLU
// 256 threads, 2 CTAs/SM (96KB smem). Q via small per-block global roundtrip.
// ===========================================================================
__global__ __launch_bounds__(256, 2) void tatt_fused(
    const float* __restrict__ x,  const float* __restrict__ tem,
    const float* __restrict__ bq, const float* __restrict__ bk,
    const float* __restrict__ bv, const float* __restrict__ bo,
    float* __restrict__ out)
{
    u32* AFH = (u32*)(smc + SM_AFH);
    u32* AFL = (u32*)(smc + SM_AFL);
    u32* BKH = (u32*)(smc + SM_BKH);
    u32* BKL = (u32*)(smc + SM_BKL);
    u32* VBH = (u32*)(smc + SM_VBH);
    u32* VBL = (u32*)(smc + SM_VBL);
    u32* AOH = (u32*)(smc + SM_AOH);
    u32* AOL = (u32*)(smc + SM_AOL);

    const int tid = threadIdx.x, lane = tid & 31, w = tid >> 5;
    const int blk = blockIdx.x, b = blk / V_, v = blk % V_;
    const int gid = lane >> 2, tig = lane & 3;
    const u32 gofs = (u32)blk * 4096u;

    // ---- stage concat input as A-fragments (hi/lo bf16 split) [validated] ----
    for (int i = tid; i < 8192; i += 256) {
        int cp = i >> 7, t = i & 127;
        int c0 = cp << 1;
        const float* src = (c0 < 64) ? x : tem;
        const float* pb = src + ((long)((b << 6) + (c0 & 63)) * V_ + v) * T_ + t;
        float g0 = pb[0];
        float g1 = pb[(long)V_ * T_];
        int tt = t >> 4, kg = cp >> 3, tin = t & 15;
        int lane_f = ((tin & 7) << 2) + (cp & 3);
        int reg = (tin >> 3) + (((cp >> 2) & 1) << 1);
        int X = (t >> 3) & 3;
        int idx = (((tt << 3) + kg) * 4 + reg) * 32 + (lane_f ^ X);
        AFH[idx] = pack_bf(g0, g1);
        AFL[idx] = pack_bf(g0 - bfr(g0), g1 - bfr(g1));
    }
    __syncthreads();

    const int mt = w >> 1, nq = w & 1;        // 4 x 2 warp grid
    const float* bsrc[3] = {bq, bk, bv};

    // ---- three projections; epilogues: Q->global, K->smem, V->smem scatter ----
#pragma unroll 1
    for (int p = 0; p < 3; ++p) {
        const u32* WBH = gWBH + p * 4096;
        const u32* WBL = gWBL + p * 4096;

        float acc[2][4][4];
#pragma unroll
        for (int m2 = 0; m2 < 2; ++m2)
#pragma unroll
            for (int n2 = 0; n2 < 4; ++n2)
#pragma unroll
                for (int j = 0; j < 4; ++j) acc[m2][n2][j] = 0.f;

#pragma unroll
        for (int kg = 0; kg < 8; ++kg) {
            u32 Ah[2][4], Al[2][4], Bh[4][2], Bl[4][2];
#pragma unroll
            for (int m2 = 0; m2 < 2; ++m2) {
                int tt = mt * 2 + m2;
#pragma unroll
                for (int r = 0; r < 4; ++r) {
                    int X = (tt * 2 + (r & 1)) & 3;
                    int idx = ((tt * 8 + kg) * 4 + r) * 32 + (lane ^ X);
                    Ah[m2][r] = AFH[idx];
                    Al[m2][r] = AFL[idx];
                }
            }
#pragma unroll
            for (int n2 = 0; n2 < 4; ++n2) {
                int ot = nq * 4 + n2;
#pragma unroll
                for (int r = 0; r < 2; ++r) {
                    int X = ((kg * 2 + r) & 7) << 2;
                    int idx = ((ot * 8 + kg) * 2 + r) * 32 + (lane ^ X);
                    Bh[n2][r] = WBH[idx];
                    Bl[n2][r] = WBL[idx];
                }
            }
#pragma unroll
            for (int m2 = 0; m2 < 2; ++m2)
#pragma unroll
                for (int n2 = 0; n2 < 4; ++n2) {
                    mma16816(acc[m2][n2], Ah[m2], Bh[n2]);
                    mma16816(acc[m2][n2], Ah[m2], Bl[n2]);
                    mma16816(acc[m2][n2], Al[m2], Bh[n2]);
                }
        }

        if (p == 2) __syncthreads();   // all warps done reading A-frags -> V may overlay

#pragma unroll
        for (int m2 = 0; m2 < 2; ++m2)
#pragma unroll
            for (int n2 = 0; n2 < 4; ++n2) {
                int TT = mt * 2 + m2, hh = nq * 4 + n2;
                int o0 = hh * 8 + (tig << 1);
                float b0 = bsrc[p][o0], b1 = bsrc[p][o0 + 1];
                float v0 = acc[m2][n2][0] + b0, v1 = acc[m2][n2][1] + b1;
                float v2 = acc[m2][n2][2] + b0, v3 = acc[m2][n2][3] + b1;
                u32 hi, lo;
                if (p == 0) {
                    const float SC = 0.5101344248f;    // 1/sqrt(8) * log2(e)
                    v0 *= SC; v1 *= SC; v2 *= SC; v3 *= SC;
                    split2(v0, v1, hi, lo);
                    u32 i0 = gofs + (u32)(((hh * 8 + TT) * 2 + 0) * 32 + lane);
                    gAQH[i0] = hi; gAQL[i0] = lo;
                    split2(v2, v3, hi, lo);
                    u32 i1 = gofs + (u32)(((hh * 8 + TT) * 2 + 1) * 32 + lane);
                    gAQH[i1] = hi; gAQL[i1] = lo;
                } else if (p == 1) {
                    split2(v0, v1, hi, lo);
                    int i0 = (hh * 16 + TT * 2) * 32 + lane;
                    BKH[i0] = hi; BKL[i0] = lo;
                    split2(v2, v3, hi, lo);
                    int i1 = (hh * 16 + TT * 2 + 1) * 32 + lane;
                    BKH[i1] = hi; BKL[i1] = lo;
                } else {
                    // V transpose scatter into overlay region [validated R5-R8]
                    char* bh = smc + SM_VBH + hh * 2048 + TT * 256;
                    char* bl = smc + SM_VBL + hh * 2048 + TT * 256;
                    int d0 = tig << 1, d1 = d0 + 1;
                    int wo0 = d0 * 16 + ((gid >> 1) << 2) + ((gid & 1) << 1);
                    int wo1 = d1 * 16 + ((gid >> 1) << 2) + ((gid & 1) << 1);
                    vstore(bh, bl, wo0, v0);
                    vstore(bh, bl, wo1, v1);
                    vstore(bh, bl, 128 + wo0, v2);
                    vstore(bh, bl, 128 + wo1, v3);
                }
            }
    }
    __syncthreads();    // K + V smem visible; Q global visible block-wide

    // ---- attention: warp w = head h, all mi 0..7 [K2 code verbatim] ----
    float oa[8][4];
    float l0[8], l1[8];
    {
        const int h = w;
        const bool m0 = (2 * tig) <= gid;
        const bool m1 = (2 * tig + 1) <= gid;

        u32 qh[8][2], ql[8][2];
#pragma unroll
        for (int mi = 0; mi < 8; ++mi) {
            qh[mi][0] = gAQH[gofs + ((h * 8 + mi) * 2 + 0) * 32 + lane];
            qh[mi][1] = gAQH[gofs + ((h * 8 + mi) * 2 + 1) * 32 + lane];
            ql[mi][0] = gAQL[gofs + ((h * 8 + mi) * 2 + 0) * 32 + lane];
            ql[mi][1] = gAQL[gofs + ((h * 8 + mi) * 2 + 1) * 32 + lane];
        }
#pragma unroll
        for (int mi = 0; mi < 8; ++mi) {
            oa[mi][0] = oa[mi][1] = oa[mi][2] = oa[mi][3] = 0.f;
            l0[mi] = l1[mi] = 0.f;
        }

#pragma unroll
        for (int kg = 0; kg < 8; ++kg) {
            u32 kh0 = BKH[(h * 16 + 2 * kg) * 32 + lane];
            u32 kl0 = BKL[(h * 16 + 2 * kg) * 32 + lane];
            u32 kh1 = BKH[(h * 16 + 2 * kg + 1) * 32 + lane];
            u32 kl1 = BKL[(h * 16 + 2 * kg + 1) * 32 + lane];
            u32 vh[2], vl[2];
            vh[0] = VBH[((h * 8 + kg) * 2 + 0) * 32 + lane];
            vh[1] = VBH[((h * 8 + kg) * 2 + 1) * 32 + lane];
            vl[0] = VBL[((h * 8 + kg) * 2 + 0) * 32 + lane];
            vl[1] = VBL[((h * 8 + kg) * 2 + 1) * 32 + lane];

#pragma unroll
            for (int mi = 0; mi < 8; ++mi) {
                if (mi < kg) continue;               // compile-time prune
                bool diag = (mi == kg);

                float s0[4] = {0.f, 0.f, 0.f, 0.f};
                float s1[4] = {0.f, 0.f, 0.f, 0.f};
                mma16808(s0, qh[mi], kh0); mma16808(s0, ql[mi], kh0); mma16808(s0, qh[mi], kl0);
                mma16808(s1, qh[mi], kh1); mma16808(s1, ql[mi], kh1); mma16808(s1, qh[mi], kl1);

                float e00 = ex2f(s0[0]), e01 = ex2f(s0[1]);
                float e02 = ex2f(s0[2]), e03 = ex2f(s0[3]);
                float e10 = ex2f(s1[0]), e11 = ex2f(s1[1]);
                float e12 = ex2f(s1[2]), e13 = ex2f(s1[3]);
                if (diag) {
                    e00 = m0 ? e00 : 0.f; e01 = m1 ? e01 : 0.f;
                    e10 = 0.f;            e11 = 0.f;
                    e12 = m0 ? e12 : 0.f; e13 = m1 ? e13 : 0.f;
                }
                l0[mi] += (e00 + e01) + (e10 + e11);
                l1[mi] += (e02 + e03) + (e12 + e13);

                u32 ph[4], pl[4];
                split2(e00, e01, ph[0], pl[0]);
                split2(e02, e03, ph[1], pl[1]);
                split2(e10, e11, ph[2], pl[2]);
                split2(e12, e13, ph[3], pl[3]);

                mma16816(oa[mi], ph, vh);
                mma16816(oa[mi], pl, vh);
                mma16816(oa[mi], ph, vl);
            }
        }
    }
    __syncthreads();          // all warps done reading K/V regions

    // ---- normalize + write AO frags (overlay A-lo region) ----
    {
        const int h = w;
#pragma unroll
        for (int mi = 0; mi < 8; ++mi) {
            float L0 = l0[mi], L1 = l1[mi];
            L0 += __shfl_xor_sync(0xFFFFFFFFu, L0, 1);
            L0 += __shfl_xor_sync(0xFFFFFFFFu, L0, 2);
            L1 += __shfl_xor_sync(0xFFFFFFFFu, L1, 1);
            L1 += __shfl_xor_sync(0xFFFFFFFFu, L1, 2);
            float inv0 = __fdividef(1.f, L0), inv1 = __fdividef(1.f, L1);
            float r0 = oa[mi][0] * inv0, r1 = oa[mi][1] * inv0;
            float r2 = oa[mi][2] * inv1, r3 = oa[mi][3] * inv1;

            int kga = h >> 1, regb = (h & 1) << 1;
            int X0 = (mi * 2) & 3, X1 = (mi * 2 + 1) & 3;
            int base = (mi * 4 + kga) * 4;
            u32 hi, lo;
            split2(r0, r1, hi, lo);
            AOH[(base + regb) * 32 + (lane ^ X0)] = hi;
            AOL[(base + regb) * 32 + (lane ^ X0)] = lo;
            split2(r2, r3, hi, lo);
            AOH[(base + regb + 1) * 32 + (lane ^ X1)] = hi;
            AOL[(base + regb + 1) * 32 + (lane ^ X1)] = lo;
        }
    }
    __syncthreads();

    // ---- out projection + bias + ReLU -> global (B from gWO tables) ----
    {
        float acc[2][4][4];
#pragma unroll
        for (int m2 = 0; m2 < 2; ++m2)
#pragma unroll
            for (int n2 = 0; n2 < 4; ++n2)
#pragma unroll
                for (int j = 0; j < 4; ++j) acc[m2][n2][j] = 0.f;

#pragma unroll
        for (int kg = 0; kg < 4; ++kg) {
            u32 Ah[2][4], Al[2][4], Bh[4][2], Bl[4][2];
#pragma unroll
            for (int m2 = 0; m2 < 2; ++m2) {
                int tt = mt * 2 + m2;
#pragma unroll
                for (int r = 0; r < 4; ++r) {
                    int X = (tt * 2 + (r & 1)) & 3;
                    int idx = ((tt * 4 + kg) * 4 + r) * 32 + (lane ^ X);
                    Ah[m2][r] = AOH[idx];
                    Al[m2][r] = AOL[idx];
                }
            }
#pragma unroll
            for (int n2 = 0; n2 < 4; ++n2) {
                int ot = nq * 4 + n2;
#pragma unroll
                for (int r = 0; r < 2; ++r) {
                    int X = ((kg * 2 + r) & 7) << 2;
                    int idx = ((ot * 4 + kg) * 2 + r) * 32 + (lane ^ X);
                    Bh[n2][r] = gWOH[idx];
                    Bl[n2][r] = gWOL[idx];
                }
            }
#pragma unroll
            for (int m2 = 0; m2 < 2; ++m2)
#pragma unroll
                for (int n2 = 0; n2 < 4; ++n2) {
                    mma16816(acc[m2][n2], Ah[m2], Bh[n2]);
                    mma16816(acc[m2][n2], Ah[m2], Bl[n2]);
                    mma16816(acc[m2][n2], Al[m2], Bh[n2]);
                }
        }

#pragma unroll
        for (int m2 = 0; m2 < 2; ++m2)
#pragma unroll
            for (int n2 = 0; n2 < 4; ++n2) {
                int t0 = ((mt * 2 + m2) << 4) + gid;
                int o0 = ((nq * 4 + n2) << 3) + (tig << 1);
                float b0 = bo[o0], b1 = bo[o0 + 1];
                long base0 = ((long)(b * 64 + o0) * V_ + v) * T_;
                long base1 = base0 + (long)V_ * T_;
                out[base0 + t0]     = fmaxf(acc[m2][n2][0] + b0, 0.f);
                out[base1 + t0]     = fmaxf(acc[m2][n2][1] + b1, 0.f);
                out[base0 + t0 + 8] = fmaxf(acc[m2][n2][2] + b0, 0.f);
                out[base1 + t0 + 8] = fmaxf(acc[m2][n2][3] + b1, 0.f);
            }
    }
}

// ---------------------------------------------------------------------------
extern "C" void kernel_launch(void* const* d_in, const int* in_sizes, int n_in,
                              void* d_out, int out_size)
{
    (void)in_sizes; (void)n_in; (void)out_size;
    const float* x  = (const float*)d_in[0];
    const float* te = (const float*)d_in[1];
    const float* Wq = (const float*)d_in[2];
    const float* bq = (const float*)d_in[3];
    const float* Wk = (const float*)d_in[4];
    const float* bk = (const float*)d_in[5];
    const float* Wv = (const float*)d_in[6];
    const float* bv = (const float*)d_in[7];
    const float* Wo = (const float*)d_in[8];
    const float* bo = (const float*)d_in[9];
    float* out = (float*)d_out;

    cudaFuncSetAttribute(tatt_fused, cudaFuncAttributeMaxDynamicSharedMemorySize, SMEM_TOTAL);

    prep_w<<<4, 1024>>>(Wq, Wk, Wv, Wo);
    tatt_fused<<<NBLK, 256, SMEM_TOTAL>>>(x, te, bq, bk, bv, bo, out);
}

// round 12
// speedup vs baseline: 3.0817x; 1.2506x over previous
#include <cuda_runtime.h>
#include <cuda_fp16.h>
#include <cstdint>

typedef unsigned long long u64;
typedef unsigned int       u32;

#define B_   8
#define V_   200
#define T_   128
#define NBLK (B_ * V_)          // 1600

// ---- global scratch: Q frags per block + pre-fragmented weights (fp16) ----
__device__ __align__(16) u32 gAQH[NBLK * 4096];
__device__ __align__(16) u32 gAQL[NBLK * 4096];
__device__ __align__(16) u32 gWBH[3 * 4096];
__device__ __align__(16) u32 gWOH[2048];

// ---- fused-kernel smem (bytes) ----
// [0,32768)      AFH  (overlay after p=2 mainloop: VBH @0, 16KB)
// [32768,65536)  AFL  (overlay after attention: AOH @32768, AOL @49152)
// [65536,81920)  BKH  (K single fp16)
#define SM_AFH  0
#define SM_AFL  32768
#define SM_VBH  0
#define SM_AOH  32768
#define SM_AOL  49152
#define SM_BKH  65536
#define SMEM_TOTAL 81920

// ---- helpers (fp16) ----
__device__ __forceinline__ u32 pack_h2(float a, float b) {
    __half2 h = __floats2half2_rn(a, b);
    return *(u32*)&h;
}
__device__ __forceinline__ void split2h(float a, float b, u32& hi, u32& lo) {
    hi = pack_h2(a, b);
    float ra = __half2float(__ushort_as_half((unsigned short)(hi & 0xFFFFu)));
    float rb = __half2float(__ushort_as_half((unsigned short)(hi >> 16)));
    lo = pack_h2(a - ra, b - rb);
}
__device__ __forceinline__ float ex2f(float x) {
    float y; asm("ex2.approx.f32 %0, %1;" : "=f"(y) : "f"(x)); return y;
}
// m16n8k16 row.col f16 -> f32, D += A*B
__device__ __forceinline__ void mma16816h(float* c, const u32* a, const u32* b) {
    asm volatile(
        "mma.sync.aligned.m16n8k16.row.col.f32.f16.f16.f32 "
        "{%0,%1,%2,%3}, {%4,%5,%6,%7}, {%8,%9}, {%0,%1,%2,%3};"
        : "+f"(c[0]), "+f"(c[1]), "+f"(c[2]), "+f"(c[3])
        : "r"(a[0]), "r"(a[1]), "r"(a[2]), "r"(a[3]), "r"(b[0]), "r"(b[1]));
}
// m16n8k8 row.col f16 -> f32, D += A*B
__device__ __forceinline__ void mma16808h(float* c, const u32* a, u32 b) {
    asm volatile(
        "mma.sync.aligned.m16n8k8.row.col.f32.f16.f16.f32 "
        "{%0,%1,%2,%3}, {%4,%5}, {%6}, {%0,%1,%2,%3};"
        : "+f"(c[0]), "+f"(c[1]), "+f"(c[2]), "+f"(c[3])
        : "r"(a[0]), "r"(a[1]), "r"(b));
}
__device__ __forceinline__ void vstoreh(char* bh, int off, float v) {
    *(__half*)(bh + off) = __float2half_rn(v);
}

extern __shared__ char smc[];

// ===========================================================================
// Kernel 0: pre-fragment weights into global fp16 tables (validated layouts)
// ===========================================================================
__global__ void prep_w(const float* __restrict__ Wq, const float* __restrict__ Wk,
                       const float* __restrict__ Wv, const float* __restrict__ Wo)
{
    const int p = blockIdx.x, tid = threadIdx.x;
    if (p < 3) {
        const float* W = (p == 0) ? Wq : (p == 1 ? Wk : Wv);
        for (int i = tid; i < 4096; i += 1024) {
            int o = i >> 6, cp = i & 63;
            float2 g = *(const float2*)(W + o * 128 + (cp << 1));
            int kg = cp >> 3;
            int lane_f = ((o & 7) << 2) + (cp & 3);
            int reg = (cp >> 2) & 1;
            int X = ((cp >> 2) & 7) << 2;
            int idx = ((((o >> 3) << 3) + kg) * 2 + reg) * 32 + (lane_f ^ X);
            gWBH[p * 4096 + idx] = pack_h2(g.x, g.y);
        }
    } else {
        for (int i = tid; i < 2048; i += 1024) {
            int o = i >> 5, cp = i & 31;
            float2 g = *(const float2*)(Wo + (o << 6) + (cp << 1));
            int kg = cp >> 3;
            int lane_f = ((o & 7) << 2) + (cp & 3);
            int reg = (cp >> 2) & 1;
            int X = ((cp >> 2) & 7) << 2;
            int idx = ((((o >> 3) << 2) + kg) * 2 + reg) * 32 + (lane_f ^ X);
            gWOH[idx] = pack_h2(g.x, g.y);
        }
    }
}

// ===========================================================================
// Fused kernel: concat + QKV proj + causal attention + out-proj + ReLU
// 256 threads, 2 CTAs/SM (80KB smem). fp16 2-term split products.
// ===========================================================================
__global__ __launch_bounds__(256, 2) void tatt_fused(
    const float* __restrict__ x,  const float* __restrict__ tem,
    const float* __restrict__ bq, const float* __restrict__ bk,
    const float* __restrict__ bv, const float* __restrict__ bo,
    float* __restrict__ out)
{
    u32* AFH = (u32*)(smc + SM_AFH);
    u32* AFL = (u32*)(smc + SM_AFL);
    u32* BKH = (u32*)(smc + SM_BKH);
    u32* VBH = (u32*)(smc + SM_VBH);
    u32* AOH = (u32*)(smc + SM_AOH);
    u32* AOL = (u32*)(smc + SM_AOL);

    const int tid = threadIdx.x, lane = tid & 31, w = tid >> 5;
    const int blk = blockIdx.x, b = blk / V_, v = blk % V_;
    const int gid = lane >> 2, tig = lane & 3;
    const u32 gofs = (u32)blk * 4096u;

    // ---- stage concat input as A-fragments (hi/lo fp16 split) [validated idx] ----
    for (int i = tid; i < 8192; i += 256) {
        int cp = i >> 7, t = i & 127;
        int c0 = cp << 1;
        const float* src = (c0 < 64) ? x : tem;
        const float* pb = src + ((long)((b << 6) + (c0 & 63)) * V_ + v) * T_ + t;
        float g0 = pb[0];
        float g1 = pb[(long)V_ * T_];
        int tt = t >> 4, kg = cp >> 3, tin = t & 15;
        int lane_f = ((tin & 7) << 2) + (cp & 3);
        int reg = (tin >> 3) + (((cp >> 2) & 1) << 1);
        int X = (t >> 3) & 3;
        int idx = (((tt << 3) + kg) * 4 + reg) * 32 + (lane_f ^ X);
        split2h(g0, g1, AFH[idx], AFL[idx]);
    }
    __syncthreads();

    const int mt = w >> 1, nq = w & 1;        // 4 x 2 warp grid
    const float* bsrc[3] = {bq, bk, bv};

    // ---- three projections; 2-term fp16 (A split, W single) ----
#pragma unroll 1
    for (int p = 0; p < 3; ++p) {
        const u32* WBH = gWBH + p * 4096;

        float acc[2][4][4];
#pragma unroll
        for (int m2 = 0; m2 < 2; ++m2)
#pragma unroll
            for (int n2 = 0; n2 < 4; ++n2)
#pragma unroll
                for (int j = 0; j < 4; ++j) acc[m2][n2][j] = 0.f;

#pragma unroll
        for (int kg = 0; kg < 8; ++kg) {
            u32 Ah[2][4], Al[2][4], Bh[4][2];
#pragma unroll
            for (int m2 = 0; m2 < 2; ++m2) {
                int tt = mt * 2 + m2;
#pragma unroll
                for (int r = 0; r < 4; ++r) {
                    int X = (tt * 2 + (r & 1)) & 3;
                    int idx = ((tt * 8 + kg) * 4 + r) * 32 + (lane ^ X);
                    Ah[m2][r] = AFH[idx];
                    Al[m2][r] = AFL[idx];
                }
            }
#pragma unroll
            for (int n2 = 0; n2 < 4; ++n2) {
                int ot = nq * 4 + n2;
#pragma unroll
                for (int r = 0; r < 2; ++r) {
                    int X = ((kg * 2 + r) & 7) << 2;
                    int idx = ((ot * 8 + kg) * 2 + r) * 32 + (lane ^ X);
                    Bh[n2][r] = WBH[idx];
                }
            }
#pragma unroll
            for (int m2 = 0; m2 < 2; ++m2)
#pragma unroll
                for (int n2 = 0; n2 < 4; ++n2) {
                    mma16816h(acc[m2][n2], Ah[m2], Bh[n2]);
                    mma16816h(acc[m2][n2], Al[m2], Bh[n2]);
                }
        }

        if (p == 2) __syncthreads();   // all warps done reading A-frags -> V may overlay

#pragma unroll
        for (int m2 = 0; m2 < 2; ++m2)
#pragma unroll
            for (int n2 = 0; n2 < 4; ++n2) {
                int TT = mt * 2 + m2, hh = nq * 4 + n2;
                int o0 = hh * 8 + (tig << 1);
                float b0 = bsrc[p][o0], b1 = bsrc[p][o0 + 1];
                float v0 = acc[m2][n2][0] + b0, v1 = acc[m2][n2][1] + b1;
                float v2 = acc[m2][n2][2] + b0, v3 = acc[m2][n2][3] + b1;
                if (p == 0) {
                    const float SC = 0.5101344248f;    // 1/sqrt(8) * log2(e)
                    v0 *= SC; v1 *= SC; v2 *= SC; v3 *= SC;
                    u32 hi, lo;
                    split2h(v0, v1, hi, lo);
                    u32 i0 = gofs + (u32)(((hh * 8 + TT) * 2 + 0) * 32 + lane);
                    gAQH[i0] = hi; gAQL[i0] = lo;
                    split2h(v2, v3, hi, lo);
                    u32 i1 = gofs + (u32)(((hh * 8 + TT) * 2 + 1) * 32 + lane);
                    gAQH[i1] = hi; gAQL[i1] = lo;
                } else if (p == 1) {
                    // K single fp16
                    BKH[(hh * 16 + TT * 2) * 32 + lane]     = pack_h2(v0, v1);
                    BKH[(hh * 16 + TT * 2 + 1) * 32 + lane] = pack_h2(v2, v3);
                } else {
                    // V single fp16, transpose scatter [validated offsets]
                    char* bh = smc + SM_VBH + hh * 2048 + TT * 256;
                    int d0 = tig << 1, d1 = d0 + 1;
                    int wo0 = d0 * 16 + ((gid >> 1) << 2) + ((gid & 1) << 1);
                    int wo1 = d1 * 16 + ((gid >> 1) << 2) + ((gid & 1) << 1);
                    vstoreh(bh, wo0, v0);
                    vstoreh(bh, wo1, v1);
                    vstoreh(bh, 128 + wo0, v2);
                    vstoreh(bh, 128 + wo1, v3);
                }
            }
    }
    __syncthreads();    // K + V smem visible; Q global visible block-wide

    // ---- attention: warp w = head h, all mi 0..7 ----
    float oa[8][4];
    float l0[8], l1[8];
    {
        const int h = w;
        const bool m0 = (2 * tig) <= gid;
        const bool m1 = (2 * tig + 1) <= gid;

        u32 qh[8][2], ql[8][2];
#pragma unroll
        for (int mi = 0; mi < 8; ++mi) {
            qh[mi][0] = gAQH[gofs + ((h * 8 + mi) * 2 + 0) * 32 + lane];
            qh[mi][1] = gAQH[gofs + ((h * 8 + mi) * 2 + 1) * 32 + lane];
            ql[mi][0] = gAQL[gofs + ((h * 8 + mi) * 2 + 0) * 32 + lane];
            ql[mi][1] = gAQL[gofs + ((h * 8 + mi) * 2 + 1) * 32 + lane];
        }
#pragma unroll
        for (int mi = 0; mi < 8; ++mi) {
            oa[mi][0] = oa[mi][1] = oa[mi][2] = oa[mi][3] = 0.f;
            l0[mi] = l1[mi] = 0.f;
        }

#pragma unroll
        for (int kg = 0; kg < 8; ++kg) {
            u32 kh0 = BKH[(h * 16 + 2 * kg) * 32 + lane];
            u32 kh1 = BKH[(h * 16 + 2 * kg + 1) * 32 + lane];
            u32 vh[2];
            vh[0] = VBH[((h * 8 + kg) * 2 + 0) * 32 + lane];
            vh[1] = VBH[((h * 8 + kg) * 2 + 1) * 32 + lane];

#pragma unroll
            for (int mi = 0; mi < 8; ++mi) {
                if (mi < kg) continue;               // compile-time prune
                bool diag = (mi == kg);

                float s0[4] = {0.f, 0.f, 0.f, 0.f};
                float s1[4] = {0.f, 0.f, 0.f, 0.f};
                mma16808h(s0, qh[mi], kh0); mma16808h(s0, ql[mi], kh0);
                mma16808h(s1, qh[mi], kh1); mma16808h(s1, ql[mi], kh1);

                float e00 = ex2f(s0[0]), e01 = ex2f(s0[1]);
                float e02 = ex2f(s0[2]), e03 = ex2f(s0[3]);
                float e10 = ex2f(s1[0]), e11 = ex2f(s1[1]);
                float e12 = ex2f(s1[2]), e13 = ex2f(s1[3]);
                if (diag) {
                    e00 = m0 ? e00 : 0.f; e01 = m1 ? e01 : 0.f;
                    e10 = 0.f;            e11 = 0.f;
                    e12 = m0 ? e12 : 0.f; e13 = m1 ? e13 : 0.f;
                }
                l0[mi] += (e00 + e01) + (e10 + e11);
                l1[mi] += (e02 + e03) + (e12 + e13);

                u32 ph[4], pl[4];
                split2h(e00, e01, ph[0], pl[0]);
                split2h(e02, e03, ph[1], pl[1]);
                split2h(e10, e11, ph[2], pl[2]);
                split2h(e12, e13, ph[3], pl[3]);

                mma16816h(oa[mi], ph, vh);
                mma16816h(oa[mi], pl, vh);
            }
        }
    }
    __syncthreads();          // all warps done reading K/V regions

    // ---- normalize + write AO frags (hi/lo fp16, overlay A-lo region) ----
    {
        const int h = w;
#pragma unroll
        for (int mi = 0; mi < 8; ++mi) {
            float L0 = l0[mi], L1 = l1[mi];
            L0 += __shfl_xor_sync(0xFFFFFFFFu, L0, 1);
            L0 += __shfl_xor_sync(0xFFFFFFFFu, L0, 2);
            L1 += __shfl_xor_sync(0xFFFFFFFFu, L1, 1);
            L1 += __shfl_xor_sync(0xFFFFFFFFu, L1, 2);
            float inv0 = __fdividef(1.f, L0), inv1 = __fdividef(1.f, L1);
            float r0 = oa[mi][0] * inv0, r1 = oa[mi][1] * inv0;
            float r2 = oa[mi][2] * inv1, r3 = oa[mi][3] * inv1;

            int kga = h >> 1, regb = (h & 1) << 1;
            int X0 = (mi * 2) & 3, X1 = (mi * 2 + 1) & 3;
            int base = (mi * 4 + kga) * 4;
            u32 hi, lo;
            split2h(r0, r1, hi, lo);
            AOH[(base + regb) * 32 + (lane ^ X0)] = hi;
            AOL[(base + regb) * 32 + (lane ^ X0)] = lo;
            split2h(r2, r3, hi, lo);
            AOH[(base + regb + 1) * 32 + (lane ^ X1)] = hi;
            AOL[(base + regb + 1) * 32 + (lane ^ X1)] = lo;
        }
    }
    __syncthreads();

    // ---- out projection (AO split x Wo single) + bias + ReLU -> global ----
    {
        float acc[2][4][4];
#pragma unroll
        for (int m2 = 0; m2 < 2; ++m2)
#pragma unroll
            for (int n2 = 0; n2 < 4; ++n2)
#pragma unroll
                for (int j = 0; j < 4; ++j) acc[m2][n2][j] = 0.f;

#pragma unroll
        for (int kg = 0; kg < 4; ++kg) {
            u32 Ah[2][4], Al[2][4], Bh[4][2];
#pragma unroll
            for (int m2 = 0; m2 < 2; ++m2) {
                int tt = mt * 2 + m2;
#pragma unroll
                for (int r = 0; r < 4; ++r) {
                    int X = (tt * 2 + (r & 1)) & 3;
                    int idx = ((tt * 4 + kg) * 4 + r) * 32 + (lane ^ X);
                    Ah[m2][r] = AOH[idx];
                    Al[m2][r] = AOL[idx];
                }
            }
#pragma unroll
            for (int n2 = 0; n2 < 4; ++n2) {
                int ot = nq * 4 + n2;
#pragma unroll
                for (int r = 0; r < 2; ++r) {
                    int X = ((kg * 2 + r) & 7) << 2;
                    int idx = ((ot * 4 + kg) * 2 + r) * 32 + (lane ^ X);
                    Bh[n2][r] = gWOH[idx];
                }
            }
#pragma unroll
            for (int m2 = 0; m2 < 2; ++m2)
#pragma unroll
                for (int n2 = 0; n2 < 4; ++n2) {
                    mma16816h(acc[m2][n2], Ah[m2], Bh[n2]);
                    mma16816h(acc[m2][n2], Al[m2], Bh[n2]);
                }
        }

#pragma unroll
        for (int m2 = 0; m2 < 2; ++m2)
#pragma unroll
            for (int n2 = 0; n2 < 4; ++n2) {
                int t0 = ((mt * 2 + m2) << 4) + gid;
                int o0 = ((nq * 4 + n2) << 3) + (tig << 1);
                float b0 = bo[o0], b1 = bo[o0 + 1];
                long base0 = ((long)(b * 64 + o0) * V_ + v) * T_;
                long base1 = base0 + (long)V_ * T_;
                out[base0 + t0]     = fmaxf(acc[m2][n2][0] + b0, 0.f);
                out[base1 + t0]     = fmaxf(acc[m2][n2][1] + b1, 0.f);
                out[base0 + t0 + 8] = fmaxf(acc[m2][n2][2] + b0, 0.f);
                out[base1 + t0 + 8] = fmaxf(acc[m2][n2][3] + b1, 0.f);
            }
    }
}

// ---------------------------------------------------------------------------
extern "C" void kernel_launch(void* const* d_in, const int* in_sizes, int n_in,
                              void* d_out, int out_size)
{
    (void)in_sizes; (void)n_in; (void)out_size;
    const float* x  = (const float*)d_in[0];
    const float* te = (const float*)d_in[1];
    const float* Wq = (const float*)d_in[2];
    const float* bq = (const float*)d_in[3];
    const float* Wk = (const float*)d_in[4];
    const float* bk = (const float*)d_in[5];
    const float* Wv = (const float*)d_in[6];
    const float* bv = (const float*)d_in[7];
    const float* Wo = (const float*)d_in[8];
    const float* bo = (const float*)d_in[9];
    float* out = (float*)d_out;

    cudaFuncSetAttribute(tatt_fused, cudaFuncAttributeMaxDynamicSharedMemorySize, SMEM_TOTAL);

    prep_w<<<4, 1024>>>(Wq, Wk, Wv, Wo);
    tatt_fused<<<NBLK, 256, SMEM_TOTAL>>>(x, te, bq, bk, bv, bo, out);
}